// round 6
// baseline (speedup 1.0000x reference)
#include <cuda_runtime.h>

#define BB 8
#define NN 2048
#define HID 768
#define NH 4
#define VOC 15
#define ROWS (BB*NN)       // 16384
#define K2DIM (NH*HID)     // 3072

typedef unsigned long long u64;

// ---------------- packed f32x2 helpers (Blackwell FFMA2) ---------------------
__device__ __forceinline__ u64 pack2(float lo, float hi){
    u64 r; asm("mov.b64 %0, {%1, %2};" : "=l"(r) : "f"(lo), "f"(hi)); return r;
}
__device__ __forceinline__ void unpack2(u64 v, float &lo, float &hi){
    asm("mov.b64 {%0, %1}, %2;" : "=f"(lo), "=f"(hi) : "l"(v));
}
__device__ __forceinline__ void fma2(u64 &d, u64 a, u64 b){
    asm("fma.rn.f32x2 %0, %1, %2, %0;" : "+l"(d) : "l"(a), "l"(b));
}

__device__ __forceinline__ float leakyf(float x){ return x > 0.f ? x : 0.2f*x; }
__device__ __forceinline__ float eluf(float x){ return x > 0.f ? x : (__expf(x)-1.f); }

// ---------------- scratch (static device globals; no allocation) -------------
__device__ float    g_xcat[ROWS*K2DIM];     // layer-1 concat output (B,N,3072)
__device__ float    g_Wh  [ROWS*HID];       // layer-2 Wh
__device__ unsigned g_adjbits[ROWS*64];     // adjacency bitmask, 64 words/row
__device__ int      g_C   [ROWS*16];        // neighbor vocab counts (pad 16)
__device__ int      g_H   [BB*16];          // per-batch vocab histogram (fallback)
__device__ float    g_T   [NH*VOC*HID];     // embed@W per head
__device__ float    g_E   [NH*VOC*16];      // exp(leaky(t1+t2)) table (pad 16)
__device__ float    g_s1  [ROWS];
__device__ float    g_s2  [ROWS];

// ---------------- K0: zero output accumulator --------------------------------
__global__ void k_zero(float* __restrict__ out){
    int t = blockIdx.x*256 + threadIdx.x;
    if (t < BB*HID) out[t] = 0.f;
}

// ---------------- K1: T_h = embed @ W_h  (15x768 per head) -------------------
__global__ void k_T(const float* __restrict__ embed, const float* __restrict__ Wheads){
    __shared__ float emb[VOC*HID];
    int h = blockIdx.y;
    int c = blockIdx.x*128 + threadIdx.x;
    for (int i = threadIdx.x; i < VOC*HID; i += 128) emb[i] = embed[i];
    __syncthreads();
    float acc[VOC];
    #pragma unroll
    for (int v = 0; v < VOC; v++) acc[v] = 0.f;
    const float* Wp = Wheads + (size_t)h*HID*HID + c;
    for (int k = 0; k < HID; k++){
        float w = Wp[(size_t)k*HID];
        #pragma unroll
        for (int v = 0; v < VOC; v++) acc[v] += emb[v*HID + k] * w;
    }
    #pragma unroll
    for (int v = 0; v < VOC; v++) g_T[(h*VOC + v)*HID + c] = acc[v];
}

// ---------------- K2: t1/t2 and E table --------------------------------------
__global__ void k_pre2(const float* __restrict__ aheads){
    __shared__ float t1s[NH*VOC], t2s[NH*VOC];
    int t = threadIdx.x;
    if (t < NH*VOC){
        int h = t / VOC, v = t % VOC;
        const float* Tp = g_T + (h*VOC + v)*HID;
        const float* a  = aheads + h*2*HID;
        float s1 = 0.f, s2 = 0.f;
        for (int c = 0; c < HID; c++){ s1 += Tp[c]*a[c]; s2 += Tp[c]*a[HID + c]; }
        t1s[t] = s1; t2s[t] = s2;
    }
    __syncthreads();
    for (int i = t; i < NH*VOC*VOC; i += blockDim.x){
        int h = i/(VOC*VOC); int u = (i/VOC)%VOC; int v = i%VOC;
        g_E[(h*VOC + u)*16 + v] = expf(leakyf(t1s[h*VOC + u] + t2s[h*VOC + v]));
    }
}

// ---------------- K3: adjacency bitmask + neighbor vocab counts --------------
__global__ void k_adj(const int* __restrict__ nf, const int* __restrict__ adj){
    __shared__ int fs[NN];
    __shared__ unsigned vmask[VOC][64];
    int b  = blockIdx.x >> 8;          // 256 blocks per batch, 8 rows per block
    int r0 = (blockIdx.x & 255) * 8;
    int tid = threadIdx.x, lane = tid & 31, wi = tid >> 5;
    for (int i = tid; i < NN; i += 256) fs[i] = nf[b*NN + i];
    __syncthreads();
    // vocab bitmasks
    for (int w = wi*8; w < wi*8 + 8; w++){
        int fj = fs[w*32 + lane];
        #pragma unroll
        for (int v = 0; v < VOC; v++){
            unsigned m = __ballot_sync(0xffffffffu, fj == v);
            if (lane == 0) vmask[v][w] = m;
        }
    }
    __syncthreads();
    // per-batch histogram (for the all-masked fallback), written once per batch
    if ((blockIdx.x & 255) == 0 && wi == 0){
        #pragma unroll
        for (int v = 0; v < VOC; v++){
            unsigned hv = __popc(vmask[v][lane]) + __popc(vmask[v][lane + 32]);
            hv = __reduce_add_sync(0xffffffffu, hv);
            if (lane == 0) g_H[b*16 + v] = (int)hv;
        }
    }
    // one warp per row: adjacency bits + counts
    int r = r0 + wi;
    const int* arow = adj + (size_t)(b*NN + r) * NN;
    unsigned am0 = 0, am1 = 0;
    for (int ch = 0; ch < 64; ch++){
        int a = arow[ch*32 + lane];
        unsigned m = __ballot_sync(0xffffffffu, a > 0);
        if (ch == lane)      am0 = m;
        if (ch == lane + 32) am1 = m;
    }
    unsigned* abp = g_adjbits + (size_t)(b*NN + r)*64;
    abp[lane] = am0; abp[32 + lane] = am1;
    #pragma unroll
    for (int v = 0; v < VOC; v++){
        unsigned c = __popc(am0 & vmask[v][lane]) + __popc(am1 & vmask[v][lane + 32]);
        c = __reduce_add_sync(0xffffffffu, c);
        if (lane == 0) g_C[(b*NN + r)*16 + v] = (int)c;
    }
}

// ---------------- K4: layer-1 output -> xcat (K=15 GEMM + elu) ---------------
__global__ void __launch_bounds__(256) k_l1(const int* __restrict__ nf){
    __shared__ float ws[128][16];
    __shared__ float Tt[VOC][128];
    int h = blockIdx.y / 6, ct = blockIdx.y % 6;
    int grow0 = blockIdx.x * 128;
    int b = grow0 / NN;
    int tid = threadIdx.x;
    if (tid < 128){
        int grow = grow0 + tid;
        int fi = nf[grow];
        const float* Ep = g_E + (h*VOC + fi)*16;
        const int*   Cp = g_C + (size_t)grow*16;
        float cv[VOC]; float den = 0.f;
        #pragma unroll
        for (int v = 0; v < VOC; v++){ cv[v] = (float)Cp[v]; den += cv[v]*Ep[v]; }
        if (den > 0.f){
            float inv = 1.f/den;
            #pragma unroll
            for (int v = 0; v < VOC; v++) ws[tid][v] = cv[v]*Ep[v]*inv;
        } else {
            const int* Hp = g_H + b*16;
            #pragma unroll
            for (int v = 0; v < VOC; v++) ws[tid][v] = (float)Hp[v] * (1.f/(float)NN);
        }
    }
    for (int i = tid; i < VOC*128; i += 256){
        int v = i >> 7, c = i & 127;
        Tt[v][c] = g_T[(h*VOC + v)*HID + ct*128 + c];
    }
    __syncthreads();
    int tr = tid >> 4, tc = tid & 15;
    float acc[8][8];
    #pragma unroll
    for (int i = 0; i < 8; i++)
        #pragma unroll
        for (int j = 0; j < 8; j++) acc[i][j] = 0.f;
    #pragma unroll
    for (int v = 0; v < VOC; v++){
        float bb[8];
        #pragma unroll
        for (int j = 0; j < 8; j++) bb[j] = Tt[v][tc*8 + j];
        #pragma unroll
        for (int i = 0; i < 8; i++){
            float a = ws[tr*8 + i][v];
            #pragma unroll
            for (int j = 0; j < 8; j++) acc[i][j] += a*bb[j];
        }
    }
    #pragma unroll
    for (int i = 0; i < 8; i++){
        float* op = g_xcat + (size_t)(grow0 + tr*8 + i)*K2DIM + h*HID + ct*128 + tc*8;
        float4 v0 = make_float4(eluf(acc[i][0]), eluf(acc[i][1]), eluf(acc[i][2]), eluf(acc[i][3]));
        float4 v1 = make_float4(eluf(acc[i][4]), eluf(acc[i][5]), eluf(acc[i][6]), eluf(acc[i][7]));
        *(float4*)op = v0; *(float4*)(op + 4) = v1;
    }
}

// ---------------- K5: big GEMM  Wh = xcat @ W_out  (16384x768x3072) ----------
// packed-f32x2 microkernel: 8x8 outer product as 8x4 FFMA2
__global__ void __launch_bounds__(256,2) k_gemm(const float* __restrict__ Wout){
    __shared__ float As[2][16][128];
    __shared__ float Bs[2][16][128];
    int n0 = blockIdx.x * 128;
    int m0 = blockIdx.y * 128;
    int tid = threadIdx.x;
    int tr = tid >> 4, tc = tid & 15;
    int am = tid >> 1;                    // A: row within tile
    int ak = (tid & 1) * 8;               // A: k offset (8 floats)
    int bk = tid >> 4;                    // B: k row
    int bc = (tid & 15) * 8;              // B: col offset
    const float* Ap = g_xcat + (size_t)(m0 + am)*K2DIM + ak;
    const float* Bp = Wout + (size_t)bk*HID + n0 + bc;
    float4 ra0 = *(const float4*)(Ap);
    float4 ra1 = *(const float4*)(Ap + 4);
    float4 rb0 = *(const float4*)(Bp);
    float4 rb1 = *(const float4*)(Bp + 4);
    As[0][ak+0][am]=ra0.x; As[0][ak+1][am]=ra0.y; As[0][ak+2][am]=ra0.z; As[0][ak+3][am]=ra0.w;
    As[0][ak+4][am]=ra1.x; As[0][ak+5][am]=ra1.y; As[0][ak+6][am]=ra1.z; As[0][ak+7][am]=ra1.w;
    *(float4*)&Bs[0][bk][bc] = rb0; *(float4*)&Bs[0][bk][bc+4] = rb1;
    __syncthreads();
    u64 acc2[8][4];
    #pragma unroll
    for (int i = 0; i < 8; i++)
        #pragma unroll
        for (int j = 0; j < 4; j++) acc2[i][j] = 0ull;
    const int NK = K2DIM/16;  // 192
    for (int kt = 0; kt < NK; kt++){
        int cur = kt & 1, nxt = cur ^ 1;
        if (kt + 1 < NK){
            const float* Ap2 = Ap + (kt+1)*16;
            const float* Bp2 = Bp + (size_t)(kt+1)*16*HID;
            ra0 = *(const float4*)Ap2; ra1 = *(const float4*)(Ap2 + 4);
            rb0 = *(const float4*)Bp2; rb1 = *(const float4*)(Bp2 + 4);
        }
        #pragma unroll
        for (int kk = 0; kk < 16; kk++){
            float av[8];
            *(float4*)av     = *(float4*)&As[cur][kk][tr*8];
            *(float4*)(av+4) = *(float4*)&As[cur][kk][tr*8+4];
            u64 b2[4];
            ulonglong2 t0 = *(const ulonglong2*)&Bs[cur][kk][tc*8];
            ulonglong2 t1 = *(const ulonglong2*)&Bs[cur][kk][tc*8+4];
            b2[0]=t0.x; b2[1]=t0.y; b2[2]=t1.x; b2[3]=t1.y;
            #pragma unroll
            for (int i = 0; i < 8; i++){
                u64 a2 = pack2(av[i], av[i]);
                #pragma unroll
                for (int j = 0; j < 4; j++) fma2(acc2[i][j], a2, b2[j]);
            }
        }
        if (kt + 1 < NK){
            As[nxt][ak+0][am]=ra0.x; As[nxt][ak+1][am]=ra0.y; As[nxt][ak+2][am]=ra0.z; As[nxt][ak+3][am]=ra0.w;
            As[nxt][ak+4][am]=ra1.x; As[nxt][ak+5][am]=ra1.y; As[nxt][ak+6][am]=ra1.z; As[nxt][ak+7][am]=ra1.w;
            *(float4*)&Bs[nxt][bk][bc] = rb0; *(float4*)&Bs[nxt][bk][bc+4] = rb1;
        }
        __syncthreads();
    }
    float* Op = g_Wh + (size_t)(m0 + tr*8)*HID + n0 + tc*8;
    #pragma unroll
    for (int i = 0; i < 8; i++){
        float o[8];
        #pragma unroll
        for (int j = 0; j < 4; j++) unpack2(acc2[i][j], o[2*j], o[2*j+1]);
        *(float4*)(Op + (size_t)i*HID)     = make_float4(o[0], o[1], o[2], o[3]);
        *(float4*)(Op + (size_t)i*HID + 4) = make_float4(o[4], o[5], o[6], o[7]);
    }
}

// ---------------- K6: s1 = Wh . a_out[:768], s2 = Wh . a_out[768:] -----------
__global__ void k_s12(const float* __restrict__ aout){
    int tid = threadIdx.x, lane = tid & 31, wi = tid >> 5;
    int row = blockIdx.x*8 + wi;
    const float* Whp = g_Wh + (size_t)row*HID;
    float s1 = 0.f, s2 = 0.f;
    for (int c = lane; c < HID; c += 32){
        float w = Whp[c];
        s1 += w * aout[c];
        s2 += w * aout[HID + c];
    }
    #pragma unroll
    for (int o = 16; o; o >>= 1){
        s1 += __shfl_xor_sync(0xffffffffu, s1, o);
        s2 += __shfl_xor_sync(0xffffffffu, s2, o);
    }
    if (lane == 0){ g_s1[row] = s1; g_s2[row] = s2; }
}

// ---------------- K7: fused masked-softmax attention GEMM + elu + mean pool --
__global__ void __launch_bounds__(256,2) k_attn(float* __restrict__ out){
    __shared__ float Whs[32][128];
    __shared__ float Aw [32][128];
    __shared__ float denS[256];
    __shared__ float colsum[128];
    int it = blockIdx.x, ct = blockIdx.y, b = blockIdx.z;
    int tid = threadIdx.x;
    int r = tid & 127, half = tid >> 7;
    int rowbase = b*NN + it*128;
    float s1r = g_s1[rowbase + r];
    const unsigned* abp = g_adjbits + (size_t)(rowbase + r)*64;
    const float* s2p = g_s2 + b*NN;
    int lkk = tid >> 3;              // 0..31 (Wh load row)
    int lc  = (tid & 7) * 16;        // Wh load col group
    const float* WhB = g_Wh + (size_t)b*NN*HID + ct*128;
    int tr = tid >> 4, tc = tid & 15;
    if (tid < 128) colsum[tid] = 0.f;
    u64 acc2[8][4];
    #pragma unroll
    for (int i = 0; i < 8; i++)
        #pragma unroll
        for (int j = 0; j < 4; j++) acc2[i][j] = 0ull;
    float dpart = 0.f;
    for (int kt = 0; kt < 64; kt++){
        const float* wp = WhB + (size_t)(kt*32 + lkk)*HID + lc;
        float4 w0 = *(const float4*)wp;
        float4 w1 = *(const float4*)(wp + 4);
        float4 w2 = *(const float4*)(wp + 8);
        float4 w3 = *(const float4*)(wp + 12);
        // generate attention weights while loads are in flight
        unsigned word = abp[kt];
        #pragma unroll
        for (int q = 0; q < 16; q++){
            int kk = half*16 + q;
            float w = 0.f;
            if ((word >> kk) & 1u){
                w = __expf(leakyf(s1r + s2p[kt*32 + kk]));
                dpart += w;
            }
            Aw[kk][r] = w;
        }
        *(float4*)&Whs[lkk][lc]      = w0;
        *(float4*)&Whs[lkk][lc + 4]  = w1;
        *(float4*)&Whs[lkk][lc + 8]  = w2;
        *(float4*)&Whs[lkk][lc + 12] = w3;
        __syncthreads();
        #pragma unroll
        for (int kk = 0; kk < 32; kk++){
            float av[8];
            *(float4*)av     = *(float4*)&Aw[kk][tr*8];
            *(float4*)(av+4) = *(float4*)&Aw[kk][tr*8+4];
            u64 b2[4];
            ulonglong2 t0 = *(const ulonglong2*)&Whs[kk][tc*8];
            ulonglong2 t1 = *(const ulonglong2*)&Whs[kk][tc*8+4];
            b2[0]=t0.x; b2[1]=t0.y; b2[2]=t1.x; b2[3]=t1.y;
            #pragma unroll
            for (int i = 0; i < 8; i++){
                u64 a2 = pack2(av[i], av[i]);
                #pragma unroll
                for (int j = 0; j < 4; j++) fma2(acc2[i][j], a2, b2[j]);
            }
        }
        __syncthreads();
    }
    denS[tid] = dpart;
    __syncthreads();
    float csum[8];
    #pragma unroll
    for (int j = 0; j < 8; j++) csum[j] = 0.f;
    #pragma unroll
    for (int i = 0; i < 8; i++){
        int lr = tr*8 + i;
        float den = denS[lr] + denS[128 + lr];
        float inv = (den > 0.f) ? 1.f/den : 0.f;
        float o[8];
        #pragma unroll
        for (int j = 0; j < 4; j++) unpack2(acc2[i][j], o[2*j], o[2*j+1]);
        #pragma unroll
        for (int j = 0; j < 8; j++) csum[j] += eluf(o[j] * inv);
    }
    #pragma unroll
    for (int j = 0; j < 8; j++) atomicAdd(&colsum[tc*8 + j], csum[j]);
    __syncthreads();
    if (tid < 128)
        atomicAdd(&out[b*HID + ct*128 + tid], colsum[tid] * (1.f/(float)NN));
}

// ---------------- launch ------------------------------------------------------
extern "C" void kernel_launch(void* const* d_in, const int* in_sizes, int n_in,
                              void* d_out, int out_size){
    const int*   nf     = (const int*)d_in[0];
    const int*   adj    = (const int*)d_in[1];
    const float* embed  = (const float*)d_in[2];
    const float* Wheads = (const float*)d_in[3];
    const float* aheads = (const float*)d_in[4];
    const float* Wout   = (const float*)d_in[5];
    const float* aout   = (const float*)d_in[6];
    float* out = (float*)d_out;

    k_zero<<<24, 256>>>(out);
    k_T  <<<dim3(6, 4), 128>>>(embed, Wheads);
    k_pre2<<<1, 64>>>(aheads);
    k_adj<<<2048, 256>>>(nf, adj);
    k_l1 <<<dim3(128, 24), 256>>>(nf);
    k_gemm<<<dim3(6, 128), 256>>>(Wout);
    k_s12<<<2048, 256>>>(aout);
    k_attn<<<dim3(16, 6, 8), 256>>>(out);
}

// round 9
// speedup vs baseline: 1.4145x; 1.4145x over previous
#include <cuda_runtime.h>
#include <cuda_bf16.h>
#include <cstdint>

#define BB 8
#define NN 2048
#define HID 768
#define NH 4
#define VOC 15
#define ROWS (BB*NN)
#define K2DIM (NH*HID)

typedef unsigned long long u64;
typedef unsigned int u32;

__device__ __nv_bfloat16 g_xhi[(size_t)ROWS*K2DIM];
__device__ __nv_bfloat16 g_xlo[(size_t)ROWS*K2DIM];
__device__ __nv_bfloat16 g_Bhi[(size_t)HID*K2DIM];   // Wout^T hi [n][k]
__device__ __nv_bfloat16 g_Blo[(size_t)HID*K2DIM];
__device__ float    g_w1[K2DIM], g_w2[K2DIM];
__device__ float    g_Wh[(size_t)ROWS*HID];
__device__ unsigned g_adjbits[ROWS*64];
__device__ int      g_C[ROWS*16];
__device__ int      g_H[BB*16];
__device__ float    g_T[NH*VOC*HID];
__device__ float    g_E[NH*VOC*16];
__device__ float    g_s1[ROWS];
__device__ float    g_s2[ROWS];

__device__ __forceinline__ float leakyf(float x){ return x > 0.f ? x : 0.2f*x; }
__device__ __forceinline__ float eluf(float x){ return x > 0.f ? x : (__expf(x)-1.f); }

__device__ __forceinline__ u32 smem_u32(const void* p){
    u32 a; asm("{ .reg .u64 t; cvta.to.shared.u64 t, %1; cvt.u32.u64 %0, t; }" : "=r"(a) : "l"(p));
    return a;
}
__device__ __forceinline__ u64 pack2(float lo, float hi){
    u64 r; asm("mov.b64 %0, {%1, %2};" : "=l"(r) : "f"(lo), "f"(hi)); return r;
}
__device__ __forceinline__ void unpack2(u64 v, float &lo, float &hi){
    asm("mov.b64 {%0, %1}, %2;" : "=f"(lo), "=f"(hi) : "l"(v));
}
__device__ __forceinline__ void fma2(u64 &d, u64 a, u64 b){
    asm("fma.rn.f32x2 %0, %1, %2, %0;" : "+l"(d) : "l"(a), "l"(b));
}

#define LDSM4(r, ad) \
    asm volatile("ldmatrix.sync.aligned.m8n8.x4.shared.b16 {%0,%1,%2,%3}, [%4];" \
        : "=r"((r)[0]),"=r"((r)[1]),"=r"((r)[2]),"=r"((r)[3]) : "r"(ad))

#define MMA16816(c, a, b0_, b1_) \
    asm volatile("mma.sync.aligned.m16n8k16.row.col.f32.bf16.bf16.f32 " \
        "{%0,%1,%2,%3}, {%4,%5,%6,%7}, {%8,%9}, {%0,%1,%2,%3};" \
        : "+f"((c)[0]),"+f"((c)[1]),"+f"((c)[2]),"+f"((c)[3]) \
        : "r"((a)[0]),"r"((a)[1]),"r"((a)[2]),"r"((a)[3]), "r"(b0_),"r"(b1_))

// -------- K0: zero out + s1/s2 ----------------------------------------------
__global__ void k_zero(float* __restrict__ out){
    int t = blockIdx.x*256 + threadIdx.x;
    if (t < ROWS){ g_s1[t] = 0.f; g_s2[t] = 0.f; }
    if (t < BB*HID) out[t] = 0.f;
}

// -------- K1: T_h = embed @ W_h ---------------------------------------------
__global__ void k_T(const float* __restrict__ embed, const float* __restrict__ Wheads){
    __shared__ float emb[VOC*HID];
    int h = blockIdx.y;
    int c = blockIdx.x*128 + threadIdx.x;
    for (int i = threadIdx.x; i < VOC*HID; i += 128) emb[i] = embed[i];
    __syncthreads();
    float acc[VOC];
    #pragma unroll
    for (int v = 0; v < VOC; v++) acc[v] = 0.f;
    const float* Wp = Wheads + (size_t)h*HID*HID + c;
    for (int k = 0; k < HID; k++){
        float w = Wp[(size_t)k*HID];
        #pragma unroll
        for (int v = 0; v < VOC; v++) acc[v] += emb[v*HID + k] * w;
    }
    #pragma unroll
    for (int v = 0; v < VOC; v++) g_T[(h*VOC + v)*HID + c] = acc[v];
}

// -------- K2: t1/t2 and E table ---------------------------------------------
__global__ void k_pre2(const float* __restrict__ aheads){
    __shared__ float t1s[NH*VOC], t2s[NH*VOC];
    int t = threadIdx.x;
    if (t < NH*VOC){
        int h = t / VOC, v = t % VOC;
        const float* Tp = g_T + (h*VOC + v)*HID;
        const float* a  = aheads + h*2*HID;
        float s1 = 0.f, s2 = 0.f;
        for (int c = 0; c < HID; c++){ s1 += Tp[c]*a[c]; s2 += Tp[c]*a[HID + c]; }
        t1s[t] = s1; t2s[t] = s2;
    }
    __syncthreads();
    for (int i = t; i < NH*VOC*VOC; i += blockDim.x){
        int h = i/(VOC*VOC); int u = (i/VOC)%VOC; int v = i%VOC;
        g_E[(h*VOC + u)*16 + v] = expf(leakyf(t1s[h*VOC + u] + t2s[h*VOC + v]));
    }
}

// -------- K3: adjacency bitmask + neighbor vocab counts ---------------------
__global__ void k_adj(const int* __restrict__ nf, const int* __restrict__ adj){
    __shared__ int fs[NN];
    __shared__ unsigned vmask[VOC][64];
    int b  = blockIdx.x >> 8;
    int r0 = (blockIdx.x & 255) * 8;
    int tid = threadIdx.x, lane = tid & 31, wi = tid >> 5;
    for (int i = tid; i < NN; i += 256) fs[i] = nf[b*NN + i];
    __syncthreads();
    for (int w = wi*8; w < wi*8 + 8; w++){
        int fj = fs[w*32 + lane];
        #pragma unroll
        for (int v = 0; v < VOC; v++){
            unsigned m = __ballot_sync(0xffffffffu, fj == v);
            if (lane == 0) vmask[v][w] = m;
        }
    }
    __syncthreads();
    if ((blockIdx.x & 255) == 0 && wi == 0){
        #pragma unroll
        for (int v = 0; v < VOC; v++){
            unsigned hv = __popc(vmask[v][lane]) + __popc(vmask[v][lane + 32]);
            hv = __reduce_add_sync(0xffffffffu, hv);
            if (lane == 0) g_H[b*16 + v] = (int)hv;
        }
    }
    int r = r0 + wi;
    const int* arow = adj + (size_t)(b*NN + r) * NN;
    unsigned am0 = 0, am1 = 0;
    for (int ch = 0; ch < 64; ch++){
        int a = arow[ch*32 + lane];
        unsigned m = __ballot_sync(0xffffffffu, a > 0);
        if (ch == lane)      am0 = m;
        if (ch == lane + 32) am1 = m;
    }
    unsigned* abp = g_adjbits + (size_t)(b*NN + r)*64;
    abp[lane] = am0; abp[32 + lane] = am1;
    #pragma unroll
    for (int v = 0; v < VOC; v++){
        unsigned c = __popc(am0 & vmask[v][lane]) + __popc(am1 & vmask[v][lane + 32]);
        c = __reduce_add_sync(0xffffffffu, c);
        if (lane == 0) g_C[(b*NN + r)*16 + v] = (int)c;
    }
}

// -------- K_prepB: Wout^T hi/lo bf16 + w1/w2 = Wout @ a_out halves ----------
__global__ void k_prepB(const float* __restrict__ Wout, const float* __restrict__ aout){
    int wi = threadIdx.x>>5, lane = threadIdx.x&31;
    int k = blockIdx.x*8 + wi;
    float a1s = 0.f, a2s = 0.f;
    const float* Wr = Wout + (size_t)k*HID;
    for (int n = lane; n < HID; n += 32){
        float v = Wr[n];
        a1s += v*aout[n]; a2s += v*aout[HID+n];
        __nv_bfloat16 h = __float2bfloat16(v);
        float lo = v - __bfloat162float(h);
        g_Bhi[(size_t)n*K2DIM + k] = h;
        g_Blo[(size_t)n*K2DIM + k] = __float2bfloat16(lo);
    }
    #pragma unroll
    for (int o = 16; o; o >>= 1){
        a1s += __shfl_xor_sync(0xffffffffu, a1s, o);
        a2s += __shfl_xor_sync(0xffffffffu, a2s, o);
    }
    if (lane == 0){ g_w1[k] = a1s; g_w2[k] = a2s; }
}

// -------- K4: layer-1 -> bf16 hi/lo + exact fp32 s1/s2 partials -------------
__global__ void __launch_bounds__(256) k_l1(const int* __restrict__ nf){
    __shared__ float ws[128][16];
    __shared__ float Tt[VOC][128];
    __shared__ float w1s[128], w2s[128];
    int h = blockIdx.y / 6, ct = blockIdx.y % 6;
    int grow0 = blockIdx.x * 128;
    int b = grow0 / NN;
    int tid = threadIdx.x;
    int colbase = h*HID + ct*128;
    if (tid < 128){
        int grow = grow0 + tid;
        int fi = nf[grow];
        const float* Ep = g_E + (h*VOC + fi)*16;
        const int*   Cp = g_C + (size_t)grow*16;
        float cv[VOC]; float den = 0.f;
        #pragma unroll
        for (int v = 0; v < VOC; v++){ cv[v] = (float)Cp[v]; den += cv[v]*Ep[v]; }
        if (den > 0.f){
            float inv = 1.f/den;
            #pragma unroll
            for (int v = 0; v < VOC; v++) ws[tid][v] = cv[v]*Ep[v]*inv;
        } else {
            const int* Hp = g_H + b*16;
            #pragma unroll
            for (int v = 0; v < VOC; v++) ws[tid][v] = (float)Hp[v] * (1.f/(float)NN);
        }
        w1s[tid] = g_w1[colbase + tid];
        w2s[tid] = g_w2[colbase + tid];
    }
    for (int i = tid; i < VOC*128; i += 256){
        int v = i >> 7, c = i & 127;
        Tt[v][c] = g_T[(h*VOC + v)*HID + ct*128 + c];
    }
    __syncthreads();
    int tr = tid >> 4, tc = tid & 15;
    float acc[8][8];
    #pragma unroll
    for (int i = 0; i < 8; i++)
        #pragma unroll
        for (int j = 0; j < 8; j++) acc[i][j] = 0.f;
    #pragma unroll
    for (int v = 0; v < VOC; v++){
        float bb[8];
        #pragma unroll
        for (int j = 0; j < 8; j++) bb[j] = Tt[v][tc*8 + j];
        #pragma unroll
        for (int i = 0; i < 8; i++){
            float a = ws[tr*8 + i][v];
            #pragma unroll
            for (int j = 0; j < 8; j++) acc[i][j] += a*bb[j];
        }
    }
    #pragma unroll
    for (int i = 0; i < 8; i++){
        int row = grow0 + tr*8 + i;
        size_t base = (size_t)row*K2DIM + colbase + tc*8;
        float v[8];
        #pragma unroll
        for (int j = 0; j < 8; j++) v[j] = eluf(acc[i][j]);
        float p1 = 0.f, p2 = 0.f;
        #pragma unroll
        for (int j = 0; j < 8; j++){ p1 += v[j]*w1s[tc*8+j]; p2 += v[j]*w2s[tc*8+j]; }
        u32 hw[4], lw[4];
        #pragma unroll
        for (int j2 = 0; j2 < 4; j2++){
            __nv_bfloat16 h0 = __float2bfloat16(v[2*j2]);
            __nv_bfloat16 h1 = __float2bfloat16(v[2*j2+1]);
            float l0 = v[2*j2]   - __bfloat162float(h0);
            float l1 = v[2*j2+1] - __bfloat162float(h1);
            __nv_bfloat162 hp = __halves2bfloat162(h0, h1);
            __nv_bfloat162 lp = __halves2bfloat162(__float2bfloat16(l0), __float2bfloat16(l1));
            hw[j2] = *reinterpret_cast<u32*>(&hp);
            lw[j2] = *reinterpret_cast<u32*>(&lp);
        }
        *reinterpret_cast<uint4*>(g_xhi + base) = make_uint4(hw[0],hw[1],hw[2],hw[3]);
        *reinterpret_cast<uint4*>(g_xlo + base) = make_uint4(lw[0],lw[1],lw[2],lw[3]);
        #pragma unroll
        for (int o = 8; o; o >>= 1){
            p1 += __shfl_xor_sync(0xffffffffu, p1, o);
            p2 += __shfl_xor_sync(0xffffffffu, p2, o);
        }
        if (tc == 0){ atomicAdd(&g_s1[row], p1); atomicAdd(&g_s2[row], p2); }
    }
}

// -------- K5: HMMA bf16x3 GEMM  Wh = xcat @ Wout (16384x768x3072) -----------
#define LDS2 40                      // bf16 row stride in smem (padded)
#define ASZ (128*LDS2*2)             // 10240 B per tile array
#define STG (4*ASZ)                  // 40960 B per stage
#define GMM_SMEM (2*STG)             // 81920 B

__global__ void __launch_bounds__(256,1) k_gemm_mma(){
    extern __shared__ char sm[];
    u32 smb = smem_u32(sm);
    int tid = threadIdx.x, lane = tid&31, wid = tid>>5;
    int n0 = blockIdx.x*128, m0 = blockIdx.y*128;
    int wm = (wid>>2)*64, wn = (wid&3)*32;
    float acc[4][4][4];
    #pragma unroll
    for (int a = 0; a < 4; a++)
        #pragma unroll
        for (int b = 0; b < 4; b++)
            #pragma unroll
            for (int c = 0; c < 4; c++) acc[a][b][c] = 0.f;
    // ldmatrix lane addressing
    int arow = lane & 15,                  akh = (lane>>4)*8;
    int brow = ((lane>>4)<<3)+(lane&7),    bkh = ((lane>>3)&1)*8;
    // initial stage 0 load
    #pragma unroll
    for (int it = 0; it < 2; it++){
        int ch = tid + it*256;
        int row = ch>>2, kc = (ch&3)*8;
        u32 so = (u32)(row*LDS2 + kc)*2;
        size_t ga = (size_t)(m0+row)*K2DIM + kc;
        size_t gb = (size_t)(n0+row)*K2DIM + kc;
        *(uint4*)(sm+so)         = *(const uint4*)(g_xhi+ga);
        *(uint4*)(sm+so+ASZ)     = *(const uint4*)(g_xlo+ga);
        *(uint4*)(sm+so+2*ASZ)   = *(const uint4*)(g_Bhi+gb);
        *(uint4*)(sm+so+3*ASZ)   = *(const uint4*)(g_Blo+gb);
    }
    __syncthreads();
    const int NSt = K2DIM/32;   // 96
    uint4 rg[8];
    for (int s = 0; s < NSt; s++){
        int cur = s & 1;
        if (s + 1 < NSt){
            int k0 = (s+1)*32;
            #pragma unroll
            for (int it = 0; it < 2; it++){
                int ch = tid + it*256;
                int row = ch>>2, kc = (ch&3)*8;
                size_t ga = (size_t)(m0+row)*K2DIM + k0 + kc;
                size_t gb = (size_t)(n0+row)*K2DIM + k0 + kc;
                rg[it*4+0] = *(const uint4*)(g_xhi+ga);
                rg[it*4+1] = *(const uint4*)(g_xlo+ga);
                rg[it*4+2] = *(const uint4*)(g_Bhi+gb);
                rg[it*4+3] = *(const uint4*)(g_Blo+gb);
            }
        }
        u32 sb = smb + (u32)cur*STG;
        #pragma unroll
        for (int kh = 0; kh < 2; kh++){
            u32 ah[4][4], al[4][4];
            #pragma unroll
            for (int mt = 0; mt < 4; mt++){
                u32 ad = sb + (u32)(((wm + mt*16 + arow)*LDS2) + kh*16 + akh)*2;
                LDSM4(ah[mt], ad);
                LDSM4(al[mt], ad + ASZ);
            }
            u32 bh[4][2], bl[4][2];
            #pragma unroll
            for (int g = 0; g < 2; g++){
                u32 ad = sb + 2*ASZ + (u32)(((wn + g*16 + brow)*LDS2) + kh*16 + bkh)*2;
                u32 t[4]; LDSM4(t, ad);
                bh[2*g][0]=t[0]; bh[2*g][1]=t[1]; bh[2*g+1][0]=t[2]; bh[2*g+1][1]=t[3];
                u32 t2[4]; LDSM4(t2, ad + ASZ);
                bl[2*g][0]=t2[0]; bl[2*g][1]=t2[1]; bl[2*g+1][0]=t2[2]; bl[2*g+1][1]=t2[3];
            }
            #pragma unroll
            for (int mt = 0; mt < 4; mt++)
                #pragma unroll
                for (int nt = 0; nt < 4; nt++){
                    MMA16816(acc[mt][nt], ah[mt], bh[nt][0], bh[nt][1]);
                    MMA16816(acc[mt][nt], ah[mt], bl[nt][0], bl[nt][1]);
                    MMA16816(acc[mt][nt], al[mt], bh[nt][0], bh[nt][1]);
                }
        }
        if (s + 1 < NSt){
            u32 nb = (u32)(cur^1)*STG;
            #pragma unroll
            for (int it = 0; it < 2; it++){
                int ch = tid + it*256;
                int row = ch>>2, kc = (ch&3)*8;
                u32 so = nb + (u32)(row*LDS2 + kc)*2;
                *(uint4*)(sm+so)        = rg[it*4+0];
                *(uint4*)(sm+so+ASZ)    = rg[it*4+1];
                *(uint4*)(sm+so+2*ASZ)  = rg[it*4+2];
                *(uint4*)(sm+so+3*ASZ)  = rg[it*4+3];
            }
        }
        __syncthreads();
    }
    int rbase = m0 + wm + (lane>>2);
    int cbase = n0 + wn + (lane&3)*2;
    #pragma unroll
    for (int mt = 0; mt < 4; mt++)
        #pragma unroll
        for (int nt = 0; nt < 4; nt++){
            int r = rbase + mt*16, c = cbase + nt*8;
            *(float2*)(g_Wh + (size_t)r*HID + c)     = make_float2(acc[mt][nt][0], acc[mt][nt][1]);
            *(float2*)(g_Wh + (size_t)(r+8)*HID + c) = make_float2(acc[mt][nt][2], acc[mt][nt][3]);
        }
}

// -------- K7: fused masked-softmax attention GEMM + elu + mean pool ---------
__global__ void __launch_bounds__(256,2) k_attn(float* __restrict__ out){
    __shared__ float Whs[32][128];
    __shared__ float Aw [32][128];
    __shared__ float denS[256];
    __shared__ float colsum[128];
    int it = blockIdx.x, ct = blockIdx.y, b = blockIdx.z;
    int tid = threadIdx.x;
    int r = tid & 127, half = tid >> 7;
    int rowbase = b*NN + it*128;
    float s1r = g_s1[rowbase + r];
    const unsigned* abp = g_adjbits + (size_t)(rowbase + r)*64;
    const float* s2p = g_s2 + b*NN;
    int lkk = tid >> 3;
    int lc  = (tid & 7) * 16;
    const float* WhB = g_Wh + (size_t)b*NN*HID + ct*128;
    int tr = tid >> 4, tc = tid & 15;
    if (tid < 128) colsum[tid] = 0.f;
    u64 acc2[8][4];
    #pragma unroll
    for (int i = 0; i < 8; i++)
        #pragma unroll
        for (int j = 0; j < 4; j++) acc2[i][j] = 0ull;
    float dpart = 0.f;
    for (int kt = 0; kt < 64; kt++){
        const float* wp = WhB + (size_t)(kt*32 + lkk)*HID + lc;
        float4 w0 = *(const float4*)wp;
        float4 w1 = *(const float4*)(wp + 4);
        float4 w2 = *(const float4*)(wp + 8);
        float4 w3 = *(const float4*)(wp + 12);
        unsigned word = abp[kt];
        #pragma unroll
        for (int q = 0; q < 16; q++){
            int kk = half*16 + q;
            float w = 0.f;
            if ((word >> kk) & 1u){
                w = __expf(leakyf(s1r + s2p[kt*32 + kk]));
                dpart += w;
            }
            Aw[kk][r] = w;
        }
        *(float4*)&Whs[lkk][lc]      = w0;
        *(float4*)&Whs[lkk][lc + 4]  = w1;
        *(float4*)&Whs[lkk][lc + 8]  = w2;
        *(float4*)&Whs[lkk][lc + 12] = w3;
        __syncthreads();
        #pragma unroll
        for (int kk = 0; kk < 32; kk++){
            float av[8];
            *(float4*)av     = *(float4*)&Aw[kk][tr*8];
            *(float4*)(av+4) = *(float4*)&Aw[kk][tr*8+4];
            u64 b2[4];
            ulonglong2 t0 = *(const ulonglong2*)&Whs[kk][tc*8];
            ulonglong2 t1 = *(const ulonglong2*)&Whs[kk][tc*8+4];
            b2[0]=t0.x; b2[1]=t0.y; b2[2]=t1.x; b2[3]=t1.y;
            #pragma unroll
            for (int i = 0; i < 8; i++){
                u64 a2 = pack2(av[i], av[i]);
                #pragma unroll
                for (int j = 0; j < 4; j++) fma2(acc2[i][j], a2, b2[j]);
            }
        }
        __syncthreads();
    }
    denS[tid] = dpart;
    __syncthreads();
    float csum[8];
    #pragma unroll
    for (int j = 0; j < 8; j++) csum[j] = 0.f;
    #pragma unroll
    for (int i = 0; i < 8; i++){
        int lr = tr*8 + i;
        float den = denS[lr] + denS[128 + lr];
        float inv = (den > 0.f) ? 1.f/den : 0.f;
        float o[8];
        #pragma unroll
        for (int j = 0; j < 4; j++) unpack2(acc2[i][j], o[2*j], o[2*j+1]);
        #pragma unroll
        for (int j = 0; j < 8; j++) csum[j] += eluf(o[j] * inv);
    }
    #pragma unroll
    for (int j = 0; j < 8; j++) atomicAdd(&colsum[tc*8 + j], csum[j]);
    __syncthreads();
    if (tid < 128)
        atomicAdd(&out[b*HID + ct*128 + tid], colsum[tid] * (1.f/(float)NN));
}

// -------- launch -------------------------------------------------------------
extern "C" void kernel_launch(void* const* d_in, const int* in_sizes, int n_in,
                              void* d_out, int out_size){
    const int*   nf     = (const int*)d_in[0];
    const int*   adj    = (const int*)d_in[1];
    const float* embed  = (const float*)d_in[2];
    const float* Wheads = (const float*)d_in[3];
    const float* aheads = (const float*)d_in[4];
    const float* Wout   = (const float*)d_in[5];
    const float* aout   = (const float*)d_in[6];
    float* out = (float*)d_out;

    cudaFuncSetAttribute(k_gemm_mma, cudaFuncAttributeMaxDynamicSharedMemorySize, GMM_SMEM);

    k_zero<<<64, 256>>>(out);
    k_T   <<<dim3(6, 4), 128>>>(embed, Wheads);
    k_pre2<<<1, 64>>>(aheads);
    k_adj <<<2048, 256>>>(nf, adj);
    k_prepB<<<384, 256>>>(Wout, aout);
    k_l1  <<<dim3(128, 24), 256>>>(nf);
    k_gemm_mma<<<dim3(6, 128), 256, GMM_SMEM>>>();
    k_attn<<<dim3(16, 6, 8), 256>>>(out);
}

// round 10
// speedup vs baseline: 2.2851x; 1.6155x over previous
#include <cuda_runtime.h>
#include <cuda_bf16.h>
#include <cstdint>

#define BB 8
#define NN 2048
#define HID 768
#define NH 4
#define VOC 15
#define ROWS (BB*NN)
#define K2DIM (NH*HID)

typedef unsigned long long u64;
typedef unsigned int u32;

__device__ __nv_bfloat16 g_xhi[(size_t)ROWS*K2DIM];
__device__ __nv_bfloat16 g_xlo[(size_t)ROWS*K2DIM];
__device__ __nv_bfloat16 g_Bhi[(size_t)HID*K2DIM];   // Wout^T hi [n][k]
__device__ __nv_bfloat16 g_Blo[(size_t)HID*K2DIM];
__device__ __nv_bfloat16 g_Whhi[(size_t)ROWS*HID];   // Wh bf16 hi [k][n]
__device__ __nv_bfloat16 g_Whlo[(size_t)ROWS*HID];   // Wh bf16 lo [k][n]
__device__ __nv_bfloat16 g_awhi[(size_t)ROWS*NN];    // attention weights bf16
__device__ float    g_den[ROWS];
__device__ float    g_w1[K2DIM], g_w2[K2DIM];
__device__ unsigned g_adjbits[ROWS*64];
__device__ int      g_C[ROWS*16];
__device__ int      g_H[BB*16];
__device__ float    g_T[NH*VOC*HID];
__device__ float    g_E[NH*VOC*16];
__device__ float    g_s1[ROWS];
__device__ float    g_s2[ROWS];

__device__ __forceinline__ float leakyf(float x){ return x > 0.f ? x : 0.2f*x; }
__device__ __forceinline__ float eluf(float x){ return x > 0.f ? x : (__expf(x)-1.f); }

__device__ __forceinline__ u32 smem_u32(const void* p){
    u32 a; asm("{ .reg .u64 t; cvta.to.shared.u64 t, %1; cvt.u32.u64 %0, t; }" : "=r"(a) : "l"(p));
    return a;
}

#define LDSM4(r, ad) \
    asm volatile("ldmatrix.sync.aligned.m8n8.x4.shared.b16 {%0,%1,%2,%3}, [%4];" \
        : "=r"((r)[0]),"=r"((r)[1]),"=r"((r)[2]),"=r"((r)[3]) : "r"(ad))
#define LDSM4T(r, ad) \
    asm volatile("ldmatrix.sync.aligned.m8n8.x4.trans.shared.b16 {%0,%1,%2,%3}, [%4];" \
        : "=r"((r)[0]),"=r"((r)[1]),"=r"((r)[2]),"=r"((r)[3]) : "r"(ad))
#define MMA16816(c, a, b0_, b1_) \
    asm volatile("mma.sync.aligned.m16n8k16.row.col.f32.bf16.bf16.f32 " \
        "{%0,%1,%2,%3}, {%4,%5,%6,%7}, {%8,%9}, {%0,%1,%2,%3};" \
        : "+f"((c)[0]),"+f"((c)[1]),"+f"((c)[2]),"+f"((c)[3]) \
        : "r"((a)[0]),"r"((a)[1]),"r"((a)[2]),"r"((a)[3]), "r"(b0_),"r"(b1_))

// -------- K0: zero out + s1/s2 ----------------------------------------------
__global__ void k_zero(float* __restrict__ out){
    int t = blockIdx.x*256 + threadIdx.x;
    if (t < ROWS){ g_s1[t] = 0.f; g_s2[t] = 0.f; }
    if (t < BB*HID) out[t] = 0.f;
}

// -------- K1: T_h = embed @ W_h ---------------------------------------------
__global__ void k_T(const float* __restrict__ embed, const float* __restrict__ Wheads){
    __shared__ float emb[VOC*HID];
    int h = blockIdx.y;
    int c = blockIdx.x*128 + threadIdx.x;
    for (int i = threadIdx.x; i < VOC*HID; i += 128) emb[i] = embed[i];
    __syncthreads();
    float acc[VOC];
    #pragma unroll
    for (int v = 0; v < VOC; v++) acc[v] = 0.f;
    const float* Wp = Wheads + (size_t)h*HID*HID + c;
    for (int k = 0; k < HID; k++){
        float w = Wp[(size_t)k*HID];
        #pragma unroll
        for (int v = 0; v < VOC; v++) acc[v] += emb[v*HID + k] * w;
    }
    #pragma unroll
    for (int v = 0; v < VOC; v++) g_T[(h*VOC + v)*HID + c] = acc[v];
}

// -------- K2: t1/t2 and E table ---------------------------------------------
__global__ void k_pre2(const float* __restrict__ aheads){
    __shared__ float t1s[NH*VOC], t2s[NH*VOC];
    int t = threadIdx.x;
    if (t < NH*VOC){
        int h = t / VOC, v = t % VOC;
        const float* Tp = g_T + (h*VOC + v)*HID;
        const float* a  = aheads + h*2*HID;
        float s1 = 0.f, s2 = 0.f;
        for (int c = 0; c < HID; c++){ s1 += Tp[c]*a[c]; s2 += Tp[c]*a[HID + c]; }
        t1s[t] = s1; t2s[t] = s2;
    }
    __syncthreads();
    for (int i = t; i < NH*VOC*VOC; i += blockDim.x){
        int h = i/(VOC*VOC); int u = (i/VOC)%VOC; int v = i%VOC;
        g_E[(h*VOC + u)*16 + v] = expf(leakyf(t1s[h*VOC + u] + t2s[h*VOC + v]));
    }
}

// -------- K3: adjacency bitmask + neighbor vocab counts ---------------------
__global__ void k_adj(const int* __restrict__ nf, const int* __restrict__ adj){
    __shared__ int fs[NN];
    __shared__ unsigned vmask[VOC][64];
    int b  = blockIdx.x >> 8;
    int r0 = (blockIdx.x & 255) * 8;
    int tid = threadIdx.x, lane = tid & 31, wi = tid >> 5;
    for (int i = tid; i < NN; i += 256) fs[i] = nf[b*NN + i];
    __syncthreads();
    for (int w = wi*8; w < wi*8 + 8; w++){
        int fj = fs[w*32 + lane];
        #pragma unroll
        for (int v = 0; v < VOC; v++){
            unsigned m = __ballot_sync(0xffffffffu, fj == v);
            if (lane == 0) vmask[v][w] = m;
        }
    }
    __syncthreads();
    if ((blockIdx.x & 255) == 0 && wi == 0){
        #pragma unroll
        for (int v = 0; v < VOC; v++){
            unsigned hv = __popc(vmask[v][lane]) + __popc(vmask[v][lane + 32]);
            hv = __reduce_add_sync(0xffffffffu, hv);
            if (lane == 0) g_H[b*16 + v] = (int)hv;
        }
    }
    int r = r0 + wi;
    const int* arow = adj + (size_t)(b*NN + r) * NN;
    unsigned am0 = 0, am1 = 0;
    for (int ch = 0; ch < 64; ch++){
        int a = arow[ch*32 + lane];
        unsigned m = __ballot_sync(0xffffffffu, a > 0);
        if (ch == lane)      am0 = m;
        if (ch == lane + 32) am1 = m;
    }
    unsigned* abp = g_adjbits + (size_t)(b*NN + r)*64;
    abp[lane] = am0; abp[32 + lane] = am1;
    #pragma unroll
    for (int v = 0; v < VOC; v++){
        unsigned c = __popc(am0 & vmask[v][lane]) + __popc(am1 & vmask[v][lane + 32]);
        c = __reduce_add_sync(0xffffffffu, c);
        if (lane == 0) g_C[(b*NN + r)*16 + v] = (int)c;
    }
}

// -------- K_prepB: Wout^T hi/lo bf16 + w1/w2 = Wout @ a_out halves ----------
__global__ void k_prepB(const float* __restrict__ Wout, const float* __restrict__ aout){
    int wi = threadIdx.x>>5, lane = threadIdx.x&31;
    int k = blockIdx.x*8 + wi;
    float a1s = 0.f, a2s = 0.f;
    const float* Wr = Wout + (size_t)k*HID;
    for (int n = lane; n < HID; n += 32){
        float v = Wr[n];
        a1s += v*aout[n]; a2s += v*aout[HID+n];
        __nv_bfloat16 h = __float2bfloat16(v);
        float lo = v - __bfloat162float(h);
        g_Bhi[(size_t)n*K2DIM + k] = h;
        g_Blo[(size_t)n*K2DIM + k] = __float2bfloat16(lo);
    }
    #pragma unroll
    for (int o = 16; o; o >>= 1){
        a1s += __shfl_xor_sync(0xffffffffu, a1s, o);
        a2s += __shfl_xor_sync(0xffffffffu, a2s, o);
    }
    if (lane == 0){ g_w1[k] = a1s; g_w2[k] = a2s; }
}

// -------- K4: layer-1 -> bf16 hi/lo + exact fp32 s1/s2 partials -------------
__global__ void __launch_bounds__(256) k_l1(const int* __restrict__ nf){
    __shared__ float ws[128][16];
    __shared__ float Tt[VOC][128];
    __shared__ float w1s[128], w2s[128];
    int h = blockIdx.y / 6, ct = blockIdx.y % 6;
    int grow0 = blockIdx.x * 128;
    int b = grow0 / NN;
    int tid = threadIdx.x;
    int colbase = h*HID + ct*128;
    if (tid < 128){
        int grow = grow0 + tid;
        int fi = nf[grow];
        const float* Ep = g_E + (h*VOC + fi)*16;
        const int*   Cp = g_C + (size_t)grow*16;
        float cv[VOC]; float den = 0.f;
        #pragma unroll
        for (int v = 0; v < VOC; v++){ cv[v] = (float)Cp[v]; den += cv[v]*Ep[v]; }
        if (den > 0.f){
            float inv = 1.f/den;
            #pragma unroll
            for (int v = 0; v < VOC; v++) ws[tid][v] = cv[v]*Ep[v]*inv;
        } else {
            const int* Hp = g_H + b*16;
            #pragma unroll
            for (int v = 0; v < VOC; v++) ws[tid][v] = (float)Hp[v] * (1.f/(float)NN);
        }
        w1s[tid] = g_w1[colbase + tid];
        w2s[tid] = g_w2[colbase + tid];
    }
    for (int i = tid; i < VOC*128; i += 256){
        int v = i >> 7, c = i & 127;
        Tt[v][c] = g_T[(h*VOC + v)*HID + ct*128 + c];
    }
    __syncthreads();
    int tr = tid >> 4, tc = tid & 15;
    float acc[8][8];
    #pragma unroll
    for (int i = 0; i < 8; i++)
        #pragma unroll
        for (int j = 0; j < 8; j++) acc[i][j] = 0.f;
    #pragma unroll
    for (int v = 0; v < VOC; v++){
        float bb[8];
        #pragma unroll
        for (int j = 0; j < 8; j++) bb[j] = Tt[v][tc*8 + j];
        #pragma unroll
        for (int i = 0; i < 8; i++){
            float a = ws[tr*8 + i][v];
            #pragma unroll
            for (int j = 0; j < 8; j++) acc[i][j] += a*bb[j];
        }
    }
    #pragma unroll
    for (int i = 0; i < 8; i++){
        int row = grow0 + tr*8 + i;
        size_t base = (size_t)row*K2DIM + colbase + tc*8;
        float v[8];
        #pragma unroll
        for (int j = 0; j < 8; j++) v[j] = eluf(acc[i][j]);
        float p1 = 0.f, p2 = 0.f;
        #pragma unroll
        for (int j = 0; j < 8; j++){ p1 += v[j]*w1s[tc*8+j]; p2 += v[j]*w2s[tc*8+j]; }
        u32 hw[4], lw[4];
        #pragma unroll
        for (int j2 = 0; j2 < 4; j2++){
            __nv_bfloat16 h0 = __float2bfloat16(v[2*j2]);
            __nv_bfloat16 h1 = __float2bfloat16(v[2*j2+1]);
            float l0 = v[2*j2]   - __bfloat162float(h0);
            float l1 = v[2*j2+1] - __bfloat162float(h1);
            __nv_bfloat162 hp = __halves2bfloat162(h0, h1);
            __nv_bfloat162 lp = __halves2bfloat162(__float2bfloat16(l0), __float2bfloat16(l1));
            hw[j2] = *reinterpret_cast<u32*>(&hp);
            lw[j2] = *reinterpret_cast<u32*>(&lp);
        }
        *reinterpret_cast<uint4*>(g_xhi + base) = make_uint4(hw[0],hw[1],hw[2],hw[3]);
        *reinterpret_cast<uint4*>(g_xlo + base) = make_uint4(lw[0],lw[1],lw[2],lw[3]);
        #pragma unroll
        for (int o = 8; o; o >>= 1){
            p1 += __shfl_xor_sync(0xffffffffu, p1, o);
            p2 += __shfl_xor_sync(0xffffffffu, p2, o);
        }
        if (tc == 0){ atomicAdd(&g_s1[row], p1); atomicAdd(&g_s2[row], p2); }
    }
}

// -------- K5: HMMA bf16x3 GEMM -> Wh bf16 hi/lo ------------------------------
#define LDS2 40
#define ASZ (128*LDS2*2)
#define STG (4*ASZ)
#define GMM_SMEM (2*STG)

__global__ void __launch_bounds__(256,1) k_gemm_mma(){
    extern __shared__ char sm[];
    u32 smb = smem_u32(sm);
    int tid = threadIdx.x, lane = tid&31, wid = tid>>5;
    int n0 = blockIdx.x*128, m0 = blockIdx.y*128;
    int wm = (wid>>2)*64, wn = (wid&3)*32;
    float acc[4][4][4];
    #pragma unroll
    for (int a = 0; a < 4; a++)
        #pragma unroll
        for (int b = 0; b < 4; b++)
            #pragma unroll
            for (int c = 0; c < 4; c++) acc[a][b][c] = 0.f;
    int arow = lane & 15,                  akh = (lane>>4)*8;
    int brow = ((lane>>4)<<3)+(lane&7),    bkh = ((lane>>3)&1)*8;
    #pragma unroll
    for (int it = 0; it < 2; it++){
        int ch = tid + it*256;
        int row = ch>>2, kc = (ch&3)*8;
        u32 so = (u32)(row*LDS2 + kc)*2;
        size_t ga = (size_t)(m0+row)*K2DIM + kc;
        size_t gb = (size_t)(n0+row)*K2DIM + kc;
        *(uint4*)(sm+so)         = *(const uint4*)(g_xhi+ga);
        *(uint4*)(sm+so+ASZ)     = *(const uint4*)(g_xlo+ga);
        *(uint4*)(sm+so+2*ASZ)   = *(const uint4*)(g_Bhi+gb);
        *(uint4*)(sm+so+3*ASZ)   = *(const uint4*)(g_Blo+gb);
    }
    __syncthreads();
    const int NSt = K2DIM/32;
    uint4 rg[8];
    for (int s = 0; s < NSt; s++){
        int cur = s & 1;
        if (s + 1 < NSt){
            int k0 = (s+1)*32;
            #pragma unroll
            for (int it = 0; it < 2; it++){
                int ch = tid + it*256;
                int row = ch>>2, kc = (ch&3)*8;
                size_t ga = (size_t)(m0+row)*K2DIM + k0 + kc;
                size_t gb = (size_t)(n0+row)*K2DIM + k0 + kc;
                rg[it*4+0] = *(const uint4*)(g_xhi+ga);
                rg[it*4+1] = *(const uint4*)(g_xlo+ga);
                rg[it*4+2] = *(const uint4*)(g_Bhi+gb);
                rg[it*4+3] = *(const uint4*)(g_Blo+gb);
            }
        }
        u32 sb = smb + (u32)cur*STG;
        #pragma unroll
        for (int kh = 0; kh < 2; kh++){
            u32 ah[4][4], al[4][4];
            #pragma unroll
            for (int mt = 0; mt < 4; mt++){
                u32 ad = sb + (u32)(((wm + mt*16 + arow)*LDS2) + kh*16 + akh)*2;
                LDSM4(ah[mt], ad);
                LDSM4(al[mt], ad + ASZ);
            }
            u32 bh[4][2], bl[4][2];
            #pragma unroll
            for (int g = 0; g < 2; g++){
                u32 ad = sb + 2*ASZ + (u32)(((wn + g*16 + brow)*LDS2) + kh*16 + bkh)*2;
                u32 t[4]; LDSM4(t, ad);
                bh[2*g][0]=t[0]; bh[2*g][1]=t[1]; bh[2*g+1][0]=t[2]; bh[2*g+1][1]=t[3];
                u32 t2[4]; LDSM4(t2, ad + ASZ);
                bl[2*g][0]=t2[0]; bl[2*g][1]=t2[1]; bl[2*g+1][0]=t2[2]; bl[2*g+1][1]=t2[3];
            }
            #pragma unroll
            for (int mt = 0; mt < 4; mt++)
                #pragma unroll
                for (int nt = 0; nt < 4; nt++){
                    MMA16816(acc[mt][nt], ah[mt], bh[nt][0], bh[nt][1]);
                    MMA16816(acc[mt][nt], ah[mt], bl[nt][0], bl[nt][1]);
                    MMA16816(acc[mt][nt], al[mt], bh[nt][0], bh[nt][1]);
                }
        }
        if (s + 1 < NSt){
            u32 nb = (u32)(cur^1)*STG;
            #pragma unroll
            for (int it = 0; it < 2; it++){
                int ch = tid + it*256;
                int row = ch>>2, kc = (ch&3)*8;
                u32 so = nb + (u32)(row*LDS2 + kc)*2;
                *(uint4*)(sm+so)        = rg[it*4+0];
                *(uint4*)(sm+so+ASZ)    = rg[it*4+1];
                *(uint4*)(sm+so+2*ASZ)  = rg[it*4+2];
                *(uint4*)(sm+so+3*ASZ)  = rg[it*4+3];
            }
        }
        __syncthreads();
    }
    int rbase = m0 + wm + (lane>>2);
    int cbase = n0 + wn + (lane&3)*2;
    #pragma unroll
    for (int mt = 0; mt < 4; mt++)
        #pragma unroll
        for (int nt = 0; nt < 4; nt++){
            int c = cbase + nt*8;
            #pragma unroll
            for (int half = 0; half < 2; half++){
                int r = rbase + mt*16 + half*8;
                float v0 = acc[mt][nt][half*2], v1 = acc[mt][nt][half*2+1];
                __nv_bfloat16 h0 = __float2bfloat16(v0);
                __nv_bfloat16 h1 = __float2bfloat16(v1);
                __nv_bfloat162 hp = __halves2bfloat162(h0, h1);
                __nv_bfloat162 lp = __halves2bfloat162(
                    __float2bfloat16(v0 - __bfloat162float(h0)),
                    __float2bfloat16(v1 - __bfloat162float(h1)));
                *reinterpret_cast<u32*>(g_Whhi + (size_t)r*HID + c) = *reinterpret_cast<u32*>(&hp);
                *reinterpret_cast<u32*>(g_Whlo + (size_t)r*HID + c) = *reinterpret_cast<u32*>(&lp);
            }
        }
}

// -------- K6: attention weights (once) + row denominators -------------------
__global__ void k_aw(){
    int wid = threadIdx.x>>5, lane = threadIdx.x&31;
    int row = blockIdx.x*8 + wid;
    int b = row >> 11;
    float s1r = g_s1[row];
    const float* s2p = g_s2 + b*NN;
    const unsigned* abp = g_adjbits + (size_t)row*64;
    __nv_bfloat16* awp = g_awhi + (size_t)row*NN;
    float den = 0.f;
    for (int w = 0; w < 64; w++){
        unsigned word = abp[w];
        int col = w*32 + lane;
        float wv = 0.f;
        if ((word >> lane) & 1u){
            wv = __expf(leakyf(s1r + s2p[col]));
            den += wv;
        }
        awp[col] = __float2bfloat16(wv);
    }
    #pragma unroll
    for (int o = 16; o; o >>= 1) den += __shfl_xor_sync(0xffffffffu, den, o);
    if (lane == 0) g_den[row] = den;
}

// -------- K7: HMMA attention GEMM + elu + mean pool --------------------------
#define ALDA 40
#define BLDB 136
#define AT_A (128*ALDA*2)
#define AT_B (32*BLDB*2)
#define AT_ST (AT_A + 2*AT_B)
#define ATT_SMEM (2*AT_ST)

__global__ void __launch_bounds__(256,1) k_attn_mma(float* __restrict__ out){
    extern __shared__ char sm[];
    __shared__ float colsum[128];
    u32 smb = smem_u32(sm);
    int tid = threadIdx.x, lane = tid&31, wid = tid>>5;
    int it = blockIdx.x, ct = blockIdx.y, b = blockIdx.z;
    int grow0 = b*NN + it*128;
    int wm = (wid>>2)*64, wn = (wid&3)*32;
    if (tid < 128) colsum[tid] = 0.f;
    float acc[4][4][4];
    #pragma unroll
    for (int a = 0; a < 4; a++)
        #pragma unroll
        for (int b2 = 0; b2 < 4; b2++)
            #pragma unroll
            for (int c = 0; c < 4; c++) acc[a][b2][c] = 0.f;
    const __nv_bfloat16* Abase = g_awhi + (size_t)grow0*NN;
    const __nv_bfloat16* Bhib  = g_Whhi + (size_t)(b*NN)*HID + ct*128;
    const __nv_bfloat16* Blob  = g_Whlo + (size_t)(b*NN)*HID + ct*128;
    int arow = lane&15, akh = (lane>>4)*8;
    int bkr = lane&15, bnh = (lane>>4)*8;
    // stage 0
    #pragma unroll
    for (int it2 = 0; it2 < 2; it2++){
        int ch = tid + it2*256;
        int row = ch>>2, kc = (ch&3)*8;
        *(uint4*)(sm + (u32)(row*ALDA + kc)*2) = *(const uint4*)(Abase + (size_t)row*NN + kc);
        int kr = ch>>4, cc = (ch&15)*8;
        u32 so = AT_A + (u32)(kr*BLDB + cc)*2;
        *(uint4*)(sm + so)        = *(const uint4*)(Bhib + (size_t)kr*HID + cc);
        *(uint4*)(sm + so + AT_B) = *(const uint4*)(Blob + (size_t)kr*HID + cc);
    }
    __syncthreads();
    const int NSt = NN/32;  // 64
    uint4 rg[6];
    for (int s = 0; s < NSt; s++){
        int cur = s & 1;
        if (s + 1 < NSt){
            int k0 = (s+1)*32;
            #pragma unroll
            for (int it2 = 0; it2 < 2; it2++){
                int ch = tid + it2*256;
                int row = ch>>2, kc = (ch&3)*8;
                rg[it2] = *(const uint4*)(Abase + (size_t)row*NN + k0 + kc);
                int kr = ch>>4, cc = (ch&15)*8;
                rg[2+it2*2+0] = *(const uint4*)(Bhib + (size_t)(k0+kr)*HID + cc);
                rg[2+it2*2+1] = *(const uint4*)(Blob + (size_t)(k0+kr)*HID + cc);
            }
        }
        u32 sb = smb + (u32)cur*AT_ST;
        #pragma unroll
        for (int kh = 0; kh < 2; kh++){
            u32 ah[4][4];
            #pragma unroll
            for (int mt = 0; mt < 4; mt++){
                u32 ad = sb + (u32)(((wm + mt*16 + arow)*ALDA) + kh*16 + akh)*2;
                LDSM4(ah[mt], ad);
            }
            u32 bh[4][2], bl[4][2];
            #pragma unroll
            for (int g = 0; g < 2; g++){
                u32 ad = sb + AT_A + (u32)(((kh*16 + bkr)*BLDB) + wn + g*16 + bnh)*2;
                u32 t[4];  LDSM4T(t, ad);
                bh[2*g][0]=t[0]; bh[2*g][1]=t[1]; bh[2*g+1][0]=t[2]; bh[2*g+1][1]=t[3];
                u32 t2[4]; LDSM4T(t2, ad + AT_B);
                bl[2*g][0]=t2[0]; bl[2*g][1]=t2[1]; bl[2*g+1][0]=t2[2]; bl[2*g+1][1]=t2[3];
            }
            #pragma unroll
            for (int mt = 0; mt < 4; mt++)
                #pragma unroll
                for (int nt = 0; nt < 4; nt++){
                    MMA16816(acc[mt][nt], ah[mt], bh[nt][0], bh[nt][1]);
                    MMA16816(acc[mt][nt], ah[mt], bl[nt][0], bl[nt][1]);
                }
        }
        if (s + 1 < NSt){
            u32 nb = (u32)(cur^1)*AT_ST;
            #pragma unroll
            for (int it2 = 0; it2 < 2; it2++){
                int ch = tid + it2*256;
                int row = ch>>2, kc = (ch&3)*8;
                *(uint4*)(sm + nb + (u32)(row*ALDA + kc)*2) = rg[it2];
                int kr = ch>>4, cc = (ch&15)*8;
                u32 so = nb + AT_A + (u32)(kr*BLDB + cc)*2;
                *(uint4*)(sm + so)        = rg[2+it2*2+0];
                *(uint4*)(sm + so + AT_B) = rg[2+it2*2+1];
            }
        }
        __syncthreads();
    }
    float invd[4][2];
    #pragma unroll
    for (int mt = 0; mt < 4; mt++){
        int r = grow0 + wm + mt*16 + (lane>>2);
        float d0 = g_den[r], d1 = g_den[r+8];
        invd[mt][0] = d0 > 0.f ? 1.f/d0 : 0.f;
        invd[mt][1] = d1 > 0.f ? 1.f/d1 : 0.f;
    }
    #pragma unroll
    for (int nt = 0; nt < 4; nt++){
        float cs0 = 0.f, cs1 = 0.f;
        #pragma unroll
        for (int mt = 0; mt < 4; mt++){
            cs0 += eluf(acc[mt][nt][0]*invd[mt][0]) + eluf(acc[mt][nt][2]*invd[mt][1]);
            cs1 += eluf(acc[mt][nt][1]*invd[mt][0]) + eluf(acc[mt][nt][3]*invd[mt][1]);
        }
        int c = wn + nt*8 + (lane&3)*2;
        atomicAdd(&colsum[c], cs0);
        atomicAdd(&colsum[c+1], cs1);
    }
    __syncthreads();
    if (tid < 128)
        atomicAdd(&out[b*HID + ct*128 + tid], colsum[tid] * (1.f/(float)NN));
}

// -------- launch -------------------------------------------------------------
extern "C" void kernel_launch(void* const* d_in, const int* in_sizes, int n_in,
                              void* d_out, int out_size){
    const int*   nf     = (const int*)d_in[0];
    const int*   adj    = (const int*)d_in[1];
    const float* embed  = (const float*)d_in[2];
    const float* Wheads = (const float*)d_in[3];
    const float* aheads = (const float*)d_in[4];
    const float* Wout   = (const float*)d_in[5];
    const float* aout   = (const float*)d_in[6];
    float* out = (float*)d_out;

    cudaFuncSetAttribute(k_gemm_mma, cudaFuncAttributeMaxDynamicSharedMemorySize, GMM_SMEM);
    cudaFuncSetAttribute(k_attn_mma, cudaFuncAttributeMaxDynamicSharedMemorySize, ATT_SMEM);

    k_zero<<<64, 256>>>(out);
    k_T   <<<dim3(6, 4), 128>>>(embed, Wheads);
    k_pre2<<<1, 64>>>(aheads);
    k_adj <<<2048, 256>>>(nf, adj);
    k_prepB<<<384, 256>>>(Wout, aout);
    k_l1  <<<dim3(128, 24), 256>>>(nf);
    k_gemm_mma<<<dim3(6, 128), 256, GMM_SMEM>>>();
    k_aw  <<<2048, 256>>>();
    k_attn_mma<<<dim3(16, 6, 8), 256, ATT_SMEM>>>(out);
}

// round 11
// speedup vs baseline: 3.0392x; 1.3300x over previous
#include <cuda_runtime.h>
#include <cuda_bf16.h>
#include <cstdint>

#define BB 8
#define NN 2048
#define HID 768
#define NH 4
#define VOC 15
#define ROWS (BB*NN)
#define K2DIM (NH*HID)

typedef unsigned long long u64;
typedef unsigned int u32;

__device__ __nv_bfloat16 g_xhi[(size_t)ROWS*K2DIM];  // layer-1 out bf16 [m][k]
__device__ __nv_bfloat16 g_Bhi[(size_t)HID*K2DIM];   // Wout^T hi [n][k]
__device__ __nv_bfloat16 g_Blo[(size_t)HID*K2DIM];   // Wout^T lo [n][k]
__device__ __nv_bfloat16 g_Whhi[(size_t)ROWS*HID];   // Wh bf16 [k][n]
__device__ __nv_bfloat16 g_awhi[(size_t)ROWS*NN];    // attention weights bf16
__device__ float    g_den[ROWS];
__device__ float    g_w1[K2DIM], g_w2[K2DIM];
__device__ unsigned g_adjbits[ROWS*64];
__device__ int      g_C[ROWS*16];
__device__ int      g_H[BB*16];
__device__ float    g_T[NH*VOC*HID];
__device__ float    g_E[NH*VOC*16];
__device__ float    g_s1[ROWS];
__device__ float    g_s2[ROWS];

__device__ __forceinline__ float leakyf(float x){ return x > 0.f ? x : 0.2f*x; }
__device__ __forceinline__ float eluf(float x){ return x > 0.f ? x : (__expf(x)-1.f); }

__device__ __forceinline__ u32 smem_u32(const void* p){
    u32 a; asm("{ .reg .u64 t; cvta.to.shared.u64 t, %1; cvt.u32.u64 %0, t; }" : "=r"(a) : "l"(p));
    return a;
}

#define LDSM4(r, ad) \
    asm volatile("ldmatrix.sync.aligned.m8n8.x4.shared.b16 {%0,%1,%2,%3}, [%4];" \
        : "=r"((r)[0]),"=r"((r)[1]),"=r"((r)[2]),"=r"((r)[3]) : "r"(ad))
#define LDSM4T(r, ad) \
    asm volatile("ldmatrix.sync.aligned.m8n8.x4.trans.shared.b16 {%0,%1,%2,%3}, [%4];" \
        : "=r"((r)[0]),"=r"((r)[1]),"=r"((r)[2]),"=r"((r)[3]) : "r"(ad))
#define MMA16816(c, a, b0_, b1_) \
    asm volatile("mma.sync.aligned.m16n8k16.row.col.f32.bf16.bf16.f32 " \
        "{%0,%1,%2,%3}, {%4,%5,%6,%7}, {%8,%9}, {%0,%1,%2,%3};" \
        : "+f"((c)[0]),"+f"((c)[1]),"+f"((c)[2]),"+f"((c)[3]) \
        : "r"((a)[0]),"r"((a)[1]),"r"((a)[2]),"r"((a)[3]), "r"(b0_),"r"(b1_))

// -------- K0: zero out + s1/s2 ----------------------------------------------
__global__ void k_zero(float* __restrict__ out){
    int t = blockIdx.x*256 + threadIdx.x;
    if (t < ROWS){ g_s1[t] = 0.f; g_s2[t] = 0.f; }
    if (t < BB*HID) out[t] = 0.f;
}

// -------- K1: T_h = embed @ W_h ---------------------------------------------
__global__ void k_T(const float* __restrict__ embed, const float* __restrict__ Wheads){
    __shared__ float emb[VOC*HID];
    int h = blockIdx.y;
    int c = blockIdx.x*128 + threadIdx.x;
    for (int i = threadIdx.x; i < VOC*HID; i += 128) emb[i] = embed[i];
    __syncthreads();
    float acc[VOC];
    #pragma unroll
    for (int v = 0; v < VOC; v++) acc[v] = 0.f;
    const float* Wp = Wheads + (size_t)h*HID*HID + c;
    for (int k = 0; k < HID; k++){
        float w = Wp[(size_t)k*HID];
        #pragma unroll
        for (int v = 0; v < VOC; v++) acc[v] += emb[v*HID + k] * w;
    }
    #pragma unroll
    for (int v = 0; v < VOC; v++) g_T[(h*VOC + v)*HID + c] = acc[v];
}

// -------- K2: t1/t2 and E table ---------------------------------------------
__global__ void k_pre2(const float* __restrict__ aheads){
    __shared__ float t1s[NH*VOC], t2s[NH*VOC];
    int t = threadIdx.x;
    if (t < NH*VOC){
        int h = t / VOC, v = t % VOC;
        const float* Tp = g_T + (h*VOC + v)*HID;
        const float* a  = aheads + h*2*HID;
        float s1 = 0.f, s2 = 0.f;
        for (int c = 0; c < HID; c++){ s1 += Tp[c]*a[c]; s2 += Tp[c]*a[HID + c]; }
        t1s[t] = s1; t2s[t] = s2;
    }
    __syncthreads();
    for (int i = t; i < NH*VOC*VOC; i += blockDim.x){
        int h = i/(VOC*VOC); int u = (i/VOC)%VOC; int v = i%VOC;
        g_E[(h*VOC + u)*16 + v] = expf(leakyf(t1s[h*VOC + u] + t2s[h*VOC + v]));
    }
}

// -------- K3: adjacency bitmask + neighbor vocab counts ---------------------
__global__ void k_adj(const int* __restrict__ nf, const int* __restrict__ adj){
    __shared__ int fs[NN];
    __shared__ unsigned vmask[VOC][64];
    int b  = blockIdx.x >> 8;
    int r0 = (blockIdx.x & 255) * 8;
    int tid = threadIdx.x, lane = tid & 31, wi = tid >> 5;
    for (int i = tid; i < NN; i += 256) fs[i] = nf[b*NN + i];
    __syncthreads();
    for (int w = wi*8; w < wi*8 + 8; w++){
        int fj = fs[w*32 + lane];
        #pragma unroll
        for (int v = 0; v < VOC; v++){
            unsigned m = __ballot_sync(0xffffffffu, fj == v);
            if (lane == 0) vmask[v][w] = m;
        }
    }
    __syncthreads();
    if ((blockIdx.x & 255) == 0 && wi == 0){
        #pragma unroll
        for (int v = 0; v < VOC; v++){
            unsigned hv = __popc(vmask[v][lane]) + __popc(vmask[v][lane + 32]);
            hv = __reduce_add_sync(0xffffffffu, hv);
            if (lane == 0) g_H[b*16 + v] = (int)hv;
        }
    }
    int r = r0 + wi;
    const int* arow = adj + (size_t)(b*NN + r) * NN;
    unsigned am0 = 0, am1 = 0;
    for (int ch = 0; ch < 64; ch++){
        int a = arow[ch*32 + lane];
        unsigned m = __ballot_sync(0xffffffffu, a > 0);
        if (ch == lane)      am0 = m;
        if (ch == lane + 32) am1 = m;
    }
    unsigned* abp = g_adjbits + (size_t)(b*NN + r)*64;
    abp[lane] = am0; abp[32 + lane] = am1;
    #pragma unroll
    for (int v = 0; v < VOC; v++){
        unsigned c = __popc(am0 & vmask[v][lane]) + __popc(am1 & vmask[v][lane + 32]);
        c = __reduce_add_sync(0xffffffffu, c);
        if (lane == 0) g_C[(b*NN + r)*16 + v] = (int)c;
    }
}

// -------- K_prepB: Wout^T hi/lo bf16 + w1/w2 = Wout @ a_out halves ----------
__global__ void k_prepB(const float* __restrict__ Wout, const float* __restrict__ aout){
    int wi = threadIdx.x>>5, lane = threadIdx.x&31;
    int k = blockIdx.x*8 + wi;
    float a1s = 0.f, a2s = 0.f;
    const float* Wr = Wout + (size_t)k*HID;
    for (int n = lane; n < HID; n += 32){
        float v = Wr[n];
        a1s += v*aout[n]; a2s += v*aout[HID+n];
        __nv_bfloat16 h = __float2bfloat16(v);
        float lo = v - __bfloat162float(h);
        g_Bhi[(size_t)n*K2DIM + k] = h;
        g_Blo[(size_t)n*K2DIM + k] = __float2bfloat16(lo);
    }
    #pragma unroll
    for (int o = 16; o; o >>= 1){
        a1s += __shfl_xor_sync(0xffffffffu, a1s, o);
        a2s += __shfl_xor_sync(0xffffffffu, a2s, o);
    }
    if (lane == 0){ g_w1[k] = a1s; g_w2[k] = a2s; }
}

// -------- K4: layer-1 -> bf16 + exact fp32 s1/s2 partials -------------------
__global__ void __launch_bounds__(256) k_l1(const int* __restrict__ nf){
    __shared__ float ws[128][16];
    __shared__ float Tt[VOC][128];
    __shared__ float w1s[128], w2s[128];
    int h = blockIdx.y / 6, ct = blockIdx.y % 6;
    int grow0 = blockIdx.x * 128;
    int b = grow0 / NN;
    int tid = threadIdx.x;
    int colbase = h*HID + ct*128;
    if (tid < 128){
        int grow = grow0 + tid;
        int fi = nf[grow];
        const float* Ep = g_E + (h*VOC + fi)*16;
        const int*   Cp = g_C + (size_t)grow*16;
        float cv[VOC]; float den = 0.f;
        #pragma unroll
        for (int v = 0; v < VOC; v++){ cv[v] = (float)Cp[v]; den += cv[v]*Ep[v]; }
        if (den > 0.f){
            float inv = 1.f/den;
            #pragma unroll
            for (int v = 0; v < VOC; v++) ws[tid][v] = cv[v]*Ep[v]*inv;
        } else {
            const int* Hp = g_H + b*16;
            #pragma unroll
            for (int v = 0; v < VOC; v++) ws[tid][v] = (float)Hp[v] * (1.f/(float)NN);
        }
        w1s[tid] = g_w1[colbase + tid];
        w2s[tid] = g_w2[colbase + tid];
    }
    for (int i = tid; i < VOC*128; i += 256){
        int v = i >> 7, c = i & 127;
        Tt[v][c] = g_T[(h*VOC + v)*HID + ct*128 + c];
    }
    __syncthreads();
    int tr = tid >> 4, tc = tid & 15;
    float acc[8][8];
    #pragma unroll
    for (int i = 0; i < 8; i++)
        #pragma unroll
        for (int j = 0; j < 8; j++) acc[i][j] = 0.f;
    #pragma unroll
    for (int v = 0; v < VOC; v++){
        float bb[8];
        #pragma unroll
        for (int j = 0; j < 8; j++) bb[j] = Tt[v][tc*8 + j];
        #pragma unroll
        for (int i = 0; i < 8; i++){
            float a = ws[tr*8 + i][v];
            #pragma unroll
            for (int j = 0; j < 8; j++) acc[i][j] += a*bb[j];
        }
    }
    #pragma unroll
    for (int i = 0; i < 8; i++){
        int row = grow0 + tr*8 + i;
        size_t base = (size_t)row*K2DIM + colbase + tc*8;
        float v[8];
        #pragma unroll
        for (int j = 0; j < 8; j++) v[j] = eluf(acc[i][j]);
        float p1 = 0.f, p2 = 0.f;
        #pragma unroll
        for (int j = 0; j < 8; j++){ p1 += v[j]*w1s[tc*8+j]; p2 += v[j]*w2s[tc*8+j]; }
        u32 hw[4];
        #pragma unroll
        for (int j2 = 0; j2 < 4; j2++){
            __nv_bfloat162 hp = __halves2bfloat162(
                __float2bfloat16(v[2*j2]), __float2bfloat16(v[2*j2+1]));
            hw[j2] = *reinterpret_cast<u32*>(&hp);
        }
        *reinterpret_cast<uint4*>(g_xhi + base) = make_uint4(hw[0],hw[1],hw[2],hw[3]);
        #pragma unroll
        for (int o = 8; o; o >>= 1){
            p1 += __shfl_xor_sync(0xffffffffu, p1, o);
            p2 += __shfl_xor_sync(0xffffffffu, p2, o);
        }
        if (tc == 0){ atomicAdd(&g_s1[row], p1); atomicAdd(&g_s2[row], p2); }
    }
}

// -------- K5: HMMA 2-term GEMM -> Wh bf16  (A bf16, B exact hi/lo) ----------
#define LDS2 40
#define ASZ (128*LDS2*2)          // 10240
#define STG (3*ASZ)               // 30720
#define GMM_SMEM (2*STG)          // 61440

__global__ void __launch_bounds__(256,2) k_gemm_mma(){
    extern __shared__ char sm[];
    u32 smb = smem_u32(sm);
    int tid = threadIdx.x, lane = tid&31, wid = tid>>5;
    int n0 = blockIdx.x*128, m0 = blockIdx.y*128;
    int wm = (wid>>2)*64, wn = (wid&3)*32;
    float acc[4][4][4];
    #pragma unroll
    for (int a = 0; a < 4; a++)
        #pragma unroll
        for (int b = 0; b < 4; b++)
            #pragma unroll
            for (int c = 0; c < 4; c++) acc[a][b][c] = 0.f;
    int arow = lane & 15,                  akh = (lane>>4)*8;
    int brow = ((lane>>4)<<3)+(lane&7),    bkh = ((lane>>3)&1)*8;
    #pragma unroll
    for (int it = 0; it < 2; it++){
        int ch = tid + it*256;
        int row = ch>>2, kc = (ch&3)*8;
        u32 so = (u32)(row*LDS2 + kc)*2;
        size_t ga = (size_t)(m0+row)*K2DIM + kc;
        size_t gb = (size_t)(n0+row)*K2DIM + kc;
        *(uint4*)(sm+so)         = *(const uint4*)(g_xhi+ga);
        *(uint4*)(sm+so+ASZ)     = *(const uint4*)(g_Bhi+gb);
        *(uint4*)(sm+so+2*ASZ)   = *(const uint4*)(g_Blo+gb);
    }
    __syncthreads();
    const int NSt = K2DIM/32;   // 96
    uint4 rg[6];
    for (int s = 0; s < NSt; s++){
        int cur = s & 1;
        if (s + 1 < NSt){
            int k0 = (s+1)*32;
            #pragma unroll
            for (int it = 0; it < 2; it++){
                int ch = tid + it*256;
                int row = ch>>2, kc = (ch&3)*8;
                size_t ga = (size_t)(m0+row)*K2DIM + k0 + kc;
                size_t gb = (size_t)(n0+row)*K2DIM + k0 + kc;
                rg[it*3+0] = *(const uint4*)(g_xhi+ga);
                rg[it*3+1] = *(const uint4*)(g_Bhi+gb);
                rg[it*3+2] = *(const uint4*)(g_Blo+gb);
            }
        }
        u32 sb = smb + (u32)cur*STG;
        #pragma unroll
        for (int kh = 0; kh < 2; kh++){
            u32 ah[4][4];
            #pragma unroll
            for (int mt = 0; mt < 4; mt++){
                u32 ad = sb + (u32)(((wm + mt*16 + arow)*LDS2) + kh*16 + akh)*2;
                LDSM4(ah[mt], ad);
            }
            u32 bh[4][2], bl[4][2];
            #pragma unroll
            for (int g = 0; g < 2; g++){
                u32 ad = sb + ASZ + (u32)(((wn + g*16 + brow)*LDS2) + kh*16 + bkh)*2;
                u32 t[4]; LDSM4(t, ad);
                bh[2*g][0]=t[0]; bh[2*g][1]=t[1]; bh[2*g+1][0]=t[2]; bh[2*g+1][1]=t[3];
                u32 t2[4]; LDSM4(t2, ad + ASZ);
                bl[2*g][0]=t2[0]; bl[2*g][1]=t2[1]; bl[2*g+1][0]=t2[2]; bl[2*g+1][1]=t2[3];
            }
            #pragma unroll
            for (int mt = 0; mt < 4; mt++)
                #pragma unroll
                for (int nt = 0; nt < 4; nt++){
                    MMA16816(acc[mt][nt], ah[mt], bh[nt][0], bh[nt][1]);
                    MMA16816(acc[mt][nt], ah[mt], bl[nt][0], bl[nt][1]);
                }
        }
        if (s + 1 < NSt){
            u32 nb = (u32)(cur^1)*STG;
            #pragma unroll
            for (int it = 0; it < 2; it++){
                int ch = tid + it*256;
                int row = ch>>2, kc = (ch&3)*8;
                u32 so = nb + (u32)(row*LDS2 + kc)*2;
                *(uint4*)(sm+so)        = rg[it*3+0];
                *(uint4*)(sm+so+ASZ)    = rg[it*3+1];
                *(uint4*)(sm+so+2*ASZ)  = rg[it*3+2];
            }
        }
        __syncthreads();
    }
    int rbase = m0 + wm + (lane>>2);
    int cbase = n0 + wn + (lane&3)*2;
    #pragma unroll
    for (int mt = 0; mt < 4; mt++)
        #pragma unroll
        for (int nt = 0; nt < 4; nt++){
            int c = cbase + nt*8;
            #pragma unroll
            for (int half = 0; half < 2; half++){
                int r = rbase + mt*16 + half*8;
                __nv_bfloat162 hp = __halves2bfloat162(
                    __float2bfloat16(acc[mt][nt][half*2]),
                    __float2bfloat16(acc[mt][nt][half*2+1]));
                *reinterpret_cast<u32*>(g_Whhi + (size_t)r*HID + c) = *reinterpret_cast<u32*>(&hp);
            }
        }
}

// -------- K6: attention weights (once) + row denominators -------------------
__global__ void k_aw(){
    int wid = threadIdx.x>>5, lane = threadIdx.x&31;
    int row = blockIdx.x*8 + wid;
    int b = row >> 11;
    float s1r = g_s1[row];
    const float* s2p = g_s2 + b*NN;
    const unsigned* abp = g_adjbits + (size_t)row*64;
    __nv_bfloat16* awp = g_awhi + (size_t)row*NN;
    float den = 0.f;
    for (int w = 0; w < 64; w++){
        unsigned word = abp[w];
        int col = w*32 + lane;
        float wv = 0.f;
        if ((word >> lane) & 1u){
            wv = __expf(leakyf(s1r + s2p[col]));
            den += wv;
        }
        awp[col] = __float2bfloat16(wv);
    }
    #pragma unroll
    for (int o = 16; o; o >>= 1) den += __shfl_xor_sync(0xffffffffu, den, o);
    if (lane == 0) g_den[row] = den;
}

// -------- K7: HMMA attention GEMM (1 MMA/tile) + elu + mean pool ------------
#define ALDA 40
#define BLDB 136
#define AT_A (128*ALDA*2)
#define AT_B (32*BLDB*2)
#define AT_ST (AT_A + AT_B)
#define ATT_SMEM (2*AT_ST)

__global__ void __launch_bounds__(256,2) k_attn_mma(float* __restrict__ out){
    extern __shared__ char sm[];
    __shared__ float colsum[128];
    u32 smb = smem_u32(sm);
    int tid = threadIdx.x, lane = tid&31, wid = tid>>5;
    int it = blockIdx.x, ct = blockIdx.y, b = blockIdx.z;
    int grow0 = b*NN + it*128;
    int wm = (wid>>2)*64, wn = (wid&3)*32;
    if (tid < 128) colsum[tid] = 0.f;
    float acc[4][4][4];
    #pragma unroll
    for (int a = 0; a < 4; a++)
        #pragma unroll
        for (int b2 = 0; b2 < 4; b2++)
            #pragma unroll
            for (int c = 0; c < 4; c++) acc[a][b2][c] = 0.f;
    const __nv_bfloat16* Abase = g_awhi + (size_t)grow0*NN;
    const __nv_bfloat16* Bhib  = g_Whhi + (size_t)(b*NN)*HID + ct*128;
    int arow = lane&15, akh = (lane>>4)*8;
    int bkr = lane&15, bnh = (lane>>4)*8;
    #pragma unroll
    for (int it2 = 0; it2 < 2; it2++){
        int ch = tid + it2*256;
        int row = ch>>2, kc = (ch&3)*8;
        *(uint4*)(sm + (u32)(row*ALDA + kc)*2) = *(const uint4*)(Abase + (size_t)row*NN + kc);
        int kr = ch>>4, cc = (ch&15)*8;
        *(uint4*)(sm + AT_A + (u32)(kr*BLDB + cc)*2) = *(const uint4*)(Bhib + (size_t)kr*HID + cc);
    }
    __syncthreads();
    const int NSt = NN/32;  // 64
    uint4 rg[4];
    for (int s = 0; s < NSt; s++){
        int cur = s & 1;
        if (s + 1 < NSt){
            int k0 = (s+1)*32;
            #pragma unroll
            for (int it2 = 0; it2 < 2; it2++){
                int ch = tid + it2*256;
                int row = ch>>2, kc = (ch&3)*8;
                rg[it2*2+0] = *(const uint4*)(Abase + (size_t)row*NN + k0 + kc);
                int kr = ch>>4, cc = (ch&15)*8;
                rg[it2*2+1] = *(const uint4*)(Bhib + (size_t)(k0+kr)*HID + cc);
            }
        }
        u32 sb = smb + (u32)cur*AT_ST;
        #pragma unroll
        for (int kh = 0; kh < 2; kh++){
            u32 ah[4][4];
            #pragma unroll
            for (int mt = 0; mt < 4; mt++){
                u32 ad = sb + (u32)(((wm + mt*16 + arow)*ALDA) + kh*16 + akh)*2;
                LDSM4(ah[mt], ad);
            }
            u32 bh[4][2];
            #pragma unroll
            for (int g = 0; g < 2; g++){
                u32 ad = sb + AT_A + (u32)(((kh*16 + bkr)*BLDB) + wn + g*16 + bnh)*2;
                u32 t[4];  LDSM4T(t, ad);
                bh[2*g][0]=t[0]; bh[2*g][1]=t[1]; bh[2*g+1][0]=t[2]; bh[2*g+1][1]=t[3];
            }
            #pragma unroll
            for (int mt = 0; mt < 4; mt++)
                #pragma unroll
                for (int nt = 0; nt < 4; nt++)
                    MMA16816(acc[mt][nt], ah[mt], bh[nt][0], bh[nt][1]);
        }
        if (s + 1 < NSt){
            u32 nb = (u32)(cur^1)*AT_ST;
            #pragma unroll
            for (int it2 = 0; it2 < 2; it2++){
                int ch = tid + it2*256;
                int row = ch>>2, kc = (ch&3)*8;
                *(uint4*)(sm + nb + (u32)(row*ALDA + kc)*2) = rg[it2*2+0];
                int kr = ch>>4, cc = (ch&15)*8;
                *(uint4*)(sm + nb + AT_A + (u32)(kr*BLDB + cc)*2) = rg[it2*2+1];
            }
        }
        __syncthreads();
    }
    float invd[4][2];
    #pragma unroll
    for (int mt = 0; mt < 4; mt++){
        int r = grow0 + wm + mt*16 + (lane>>2);
        float d0 = g_den[r], d1 = g_den[r+8];
        invd[mt][0] = d0 > 0.f ? 1.f/d0 : 0.f;
        invd[mt][1] = d1 > 0.f ? 1.f/d1 : 0.f;
    }
    #pragma unroll
    for (int nt = 0; nt < 4; nt++){
        float cs0 = 0.f, cs1 = 0.f;
        #pragma unroll
        for (int mt = 0; mt < 4; mt++){
            cs0 += eluf(acc[mt][nt][0]*invd[mt][0]) + eluf(acc[mt][nt][2]*invd[mt][1]);
            cs1 += eluf(acc[mt][nt][1]*invd[mt][0]) + eluf(acc[mt][nt][3]*invd[mt][1]);
        }
        int c = wn + nt*8 + (lane&3)*2;
        atomicAdd(&colsum[c], cs0);
        atomicAdd(&colsum[c+1], cs1);
    }
    __syncthreads();
    if (tid < 128)
        atomicAdd(&out[b*HID + ct*128 + tid], colsum[tid] * (1.f/(float)NN));
}

// -------- launch -------------------------------------------------------------
extern "C" void kernel_launch(void* const* d_in, const int* in_sizes, int n_in,
                              void* d_out, int out_size){
    const int*   nf     = (const int*)d_in[0];
    const int*   adj    = (const int*)d_in[1];
    const float* embed  = (const float*)d_in[2];
    const float* Wheads = (const float*)d_in[3];
    const float* aheads = (const float*)d_in[4];
    const float* Wout   = (const float*)d_in[5];
    const float* aout   = (const float*)d_in[6];
    float* out = (float*)d_out;

    cudaFuncSetAttribute(k_gemm_mma, cudaFuncAttributeMaxDynamicSharedMemorySize, GMM_SMEM);
    cudaFuncSetAttribute(k_attn_mma, cudaFuncAttributeMaxDynamicSharedMemorySize, ATT_SMEM);

    k_zero<<<64, 256>>>(out);
    k_T   <<<dim3(6, 4), 128>>>(embed, Wheads);
    k_pre2<<<1, 64>>>(aheads);
    k_adj <<<2048, 256>>>(nf, adj);
    k_prepB<<<384, 256>>>(Wout, aout);
    k_l1  <<<dim3(128, 24), 256>>>(nf);
    k_gemm_mma<<<dim3(6, 128), 256, GMM_SMEM>>>();
    k_aw  <<<2048, 256>>>();
    k_attn_mma<<<dim3(16, 6, 8), 256, ATT_SMEM>>>(out);
}

// round 14
// speedup vs baseline: 3.7114x; 1.2212x over previous
#include <cuda_runtime.h>
#include <cuda_fp16.h>
#include <cstdint>

#define BB 8
#define NN 2048
#define HID 768
#define NH 4
#define VOC 15
#define ROWS (BB*NN)
#define K2DIM (NH*HID)

typedef unsigned long long u64;
typedef unsigned int u32;

__device__ __half  g_x  [(size_t)ROWS*K2DIM];  // layer-1 out fp16 [m][k]
__device__ __half  g_Bh [(size_t)HID*K2DIM];   // Wout^T fp16 [n][k]
__device__ __half  g_Wh [(size_t)ROWS*HID];    // Wh fp16 [k][n]
__device__ __half  g_aw [(size_t)ROWS*NN];     // max-shifted attn weights fp16
__device__ float   g_den[ROWS];
__device__ float   g_w1[K2DIM], g_w2[K2DIM];
__device__ unsigned g_adjbits[ROWS*64];
__device__ int     g_C[ROWS*16];
__device__ int     g_H[BB*16];
__device__ float   g_T[NH*VOC*HID];
__device__ float   g_E[NH*VOC*16];
__device__ float   g_s1[ROWS];
__device__ float   g_s2[ROWS];

__device__ __forceinline__ float leakyf(float x){ return x > 0.f ? x : 0.2f*x; }
__device__ __forceinline__ float eluf(float x){ return x > 0.f ? x : (__expf(x)-1.f); }

__device__ __forceinline__ u32 smem_u32(const void* p){
    u32 a; asm("{ .reg .u64 t; cvta.to.shared.u64 t, %1; cvt.u32.u64 %0, t; }" : "=r"(a) : "l"(p));
    return a;
}

#define LDSM4(r, ad) \
    asm volatile("ldmatrix.sync.aligned.m8n8.x4.shared.b16 {%0,%1,%2,%3}, [%4];" \
        : "=r"((r)[0]),"=r"((r)[1]),"=r"((r)[2]),"=r"((r)[3]) : "r"(ad))
#define LDSM4T(r, ad) \
    asm volatile("ldmatrix.sync.aligned.m8n8.x4.trans.shared.b16 {%0,%1,%2,%3}, [%4];" \
        : "=r"((r)[0]),"=r"((r)[1]),"=r"((r)[2]),"=r"((r)[3]) : "r"(ad))
#define MMAF16(c, a, b0_, b1_) \
    asm volatile("mma.sync.aligned.m16n8k16.row.col.f32.f16.f16.f32 " \
        "{%0,%1,%2,%3}, {%4,%5,%6,%7}, {%8,%9}, {%0,%1,%2,%3};" \
        : "+f"((c)[0]),"+f"((c)[1]),"+f"((c)[2]),"+f"((c)[3]) \
        : "r"((a)[0]),"r"((a)[1]),"r"((a)[2]),"r"((a)[3]), "r"(b0_),"r"(b1_))

// -------- K0: zero out + s1/s2 ----------------------------------------------
__global__ void k_zero(float* __restrict__ out){
    int t = blockIdx.x*256 + threadIdx.x;
    if (t < ROWS){ g_s1[t] = 0.f; g_s2[t] = 0.f; }
    if (t < BB*HID) out[t] = 0.f;
}

// -------- K1: T_h = embed @ W_h ---------------------------------------------
__global__ void k_T(const float* __restrict__ embed, const float* __restrict__ Wheads){
    __shared__ float emb[VOC*HID];
    int h = blockIdx.y;
    int c = blockIdx.x*128 + threadIdx.x;
    for (int i = threadIdx.x; i < VOC*HID; i += 128) emb[i] = embed[i];
    __syncthreads();
    float acc[VOC];
    #pragma unroll
    for (int v = 0; v < VOC; v++) acc[v] = 0.f;
    const float* Wp = Wheads + (size_t)h*HID*HID + c;
    for (int k = 0; k < HID; k++){
        float w = Wp[(size_t)k*HID];
        #pragma unroll
        for (int v = 0; v < VOC; v++) acc[v] += emb[v*HID + k] * w;
    }
    #pragma unroll
    for (int v = 0; v < VOC; v++) g_T[(h*VOC + v)*HID + c] = acc[v];
}

// -------- K2: t1/t2 and E table ---------------------------------------------
__global__ void k_pre2(const float* __restrict__ aheads){
    __shared__ float t1s[NH*VOC], t2s[NH*VOC];
    int t = threadIdx.x;
    if (t < NH*VOC){
        int h = t / VOC, v = t % VOC;
        const float* Tp = g_T + (h*VOC + v)*HID;
        const float* a  = aheads + h*2*HID;
        float s1 = 0.f, s2 = 0.f;
        for (int c = 0; c < HID; c++){ s1 += Tp[c]*a[c]; s2 += Tp[c]*a[HID + c]; }
        t1s[t] = s1; t2s[t] = s2;
    }
    __syncthreads();
    for (int i = t; i < NH*VOC*VOC; i += blockDim.x){
        int h = i/(VOC*VOC); int u = (i/VOC)%VOC; int v = i%VOC;
        g_E[(h*VOC + u)*16 + v] = expf(leakyf(t1s[h*VOC + u] + t2s[h*VOC + v]));
    }
}

// -------- K3: adjacency bitmask + neighbor vocab counts ---------------------
__global__ void k_adj(const int* __restrict__ nf, const int* __restrict__ adj){
    __shared__ int fs[NN];
    __shared__ unsigned vmask[VOC][64];
    int b  = blockIdx.x >> 8;
    int r0 = (blockIdx.x & 255) * 8;
    int tid = threadIdx.x, lane = tid & 31, wi = tid >> 5;
    for (int i = tid; i < NN; i += 256) fs[i] = nf[b*NN + i];
    __syncthreads();
    for (int w = wi*8; w < wi*8 + 8; w++){
        int fj = fs[w*32 + lane];
        #pragma unroll
        for (int v = 0; v < VOC; v++){
            unsigned m = __ballot_sync(0xffffffffu, fj == v);
            if (lane == 0) vmask[v][w] = m;
        }
    }
    __syncthreads();
    if ((blockIdx.x & 255) == 0 && wi == 0){
        #pragma unroll
        for (int v = 0; v < VOC; v++){
            unsigned hv = __popc(vmask[v][lane]) + __popc(vmask[v][lane + 32]);
            hv = __reduce_add_sync(0xffffffffu, hv);
            if (lane == 0) g_H[b*16 + v] = (int)hv;
        }
    }
    int r = r0 + wi;
    const int* arow = adj + (size_t)(b*NN + r) * NN;
    unsigned am0 = 0, am1 = 0;
    for (int ch = 0; ch < 64; ch++){
        int a = arow[ch*32 + lane];
        unsigned m = __ballot_sync(0xffffffffu, a > 0);
        if (ch == lane)      am0 = m;
        if (ch == lane + 32) am1 = m;
    }
    unsigned* abp = g_adjbits + (size_t)(b*NN + r)*64;
    abp[lane] = am0; abp[32 + lane] = am1;
    #pragma unroll
    for (int v = 0; v < VOC; v++){
        unsigned c = __popc(am0 & vmask[v][lane]) + __popc(am1 & vmask[v][lane + 32]);
        c = __reduce_add_sync(0xffffffffu, c);
        if (lane == 0) g_C[(b*NN + r)*16 + v] = (int)c;
    }
}

// -------- K_prepB: Wout^T fp16 + w1/w2 = Wout @ a_out halves ----------------
__global__ void k_prepB(const float* __restrict__ Wout, const float* __restrict__ aout){
    int wi = threadIdx.x>>5, lane = threadIdx.x&31;
    int k = blockIdx.x*8 + wi;
    float a1s = 0.f, a2s = 0.f;
    const float* Wr = Wout + (size_t)k*HID;
    for (int n = lane; n < HID; n += 32){
        float v = Wr[n];
        a1s += v*aout[n]; a2s += v*aout[HID+n];
        g_Bh[(size_t)n*K2DIM + k] = __float2half(v);
    }
    #pragma unroll
    for (int o = 16; o; o >>= 1){
        a1s += __shfl_xor_sync(0xffffffffu, a1s, o);
        a2s += __shfl_xor_sync(0xffffffffu, a2s, o);
    }
    if (lane == 0){ g_w1[k] = a1s; g_w2[k] = a2s; }
}

// -------- K4: layer-1 -> fp16 + exact fp32 s1/s2 partials -------------------
__global__ void __launch_bounds__(256) k_l1(const int* __restrict__ nf){
    __shared__ float ws[128][16];
    __shared__ float Tt[VOC][128];
    __shared__ float w1s[128], w2s[128];
    int h = blockIdx.y / 6, ct = blockIdx.y % 6;
    int grow0 = blockIdx.x * 128;
    int b = grow0 / NN;
    int tid = threadIdx.x;
    int colbase = h*HID + ct*128;
    if (tid < 128){
        int grow = grow0 + tid;
        int fi = nf[grow];
        const float* Ep = g_E + (h*VOC + fi)*16;
        const int*   Cp = g_C + (size_t)grow*16;
        float cv[VOC]; float den = 0.f;
        #pragma unroll
        for (int v = 0; v < VOC; v++){ cv[v] = (float)Cp[v]; den += cv[v]*Ep[v]; }
        if (den > 0.f){
            float inv = 1.f/den;
            #pragma unroll
            for (int v = 0; v < VOC; v++) ws[tid][v] = cv[v]*Ep[v]*inv;
        } else {
            const int* Hp = g_H + b*16;
            #pragma unroll
            for (int v = 0; v < VOC; v++) ws[tid][v] = (float)Hp[v] * (1.f/(float)NN);
        }
        w1s[tid] = g_w1[colbase + tid];
        w2s[tid] = g_w2[colbase + tid];
    }
    for (int i = tid; i < VOC*128; i += 256){
        int v = i >> 7, c = i & 127;
        Tt[v][c] = g_T[(h*VOC + v)*HID + ct*128 + c];
    }
    __syncthreads();
    int tr = tid >> 4, tc = tid & 15;
    float acc[8][8];
    #pragma unroll
    for (int i = 0; i < 8; i++)
        #pragma unroll
        for (int j = 0; j < 8; j++) acc[i][j] = 0.f;
    #pragma unroll
    for (int v = 0; v < VOC; v++){
        float bb[8];
        #pragma unroll
        for (int j = 0; j < 8; j++) bb[j] = Tt[v][tc*8 + j];
        #pragma unroll
        for (int i = 0; i < 8; i++){
            float a = ws[tr*8 + i][v];
            #pragma unroll
            for (int j = 0; j < 8; j++) acc[i][j] += a*bb[j];
        }
    }
    #pragma unroll
    for (int i = 0; i < 8; i++){
        int row = grow0 + tr*8 + i;
        size_t base = (size_t)row*K2DIM + colbase + tc*8;
        float v[8];
        #pragma unroll
        for (int j = 0; j < 8; j++) v[j] = eluf(acc[i][j]);
        float p1 = 0.f, p2 = 0.f;
        #pragma unroll
        for (int j = 0; j < 8; j++){ p1 += v[j]*w1s[tc*8+j]; p2 += v[j]*w2s[tc*8+j]; }
        u32 hw[4];
        #pragma unroll
        for (int j2 = 0; j2 < 4; j2++){
            __half2 hp = __floats2half2_rn(v[2*j2], v[2*j2+1]);
            hw[j2] = *reinterpret_cast<u32*>(&hp);
        }
        *reinterpret_cast<uint4*>(g_x + base) = make_uint4(hw[0],hw[1],hw[2],hw[3]);
        #pragma unroll
        for (int o = 8; o; o >>= 1){
            p1 += __shfl_xor_sync(0xffffffffu, p1, o);
            p2 += __shfl_xor_sync(0xffffffffu, p2, o);
        }
        if (tc == 0){ atomicAdd(&g_s1[row], p1); atomicAdd(&g_s2[row], p2); }
    }
}

// -------- K5: fp16 HMMA GEMM -> Wh fp16 (1 MMA/tile) ------------------------
#define LDS2 40
#define ASZ (128*LDS2*2)          // 10240
#define STG (2*ASZ)               // 20480
#define GMM_SMEM (2*STG)          // 40960

__global__ void __launch_bounds__(256,2) k_gemm_mma(){
    extern __shared__ char sm[];
    u32 smb = smem_u32(sm);
    int tid = threadIdx.x, lane = tid&31, wid = tid>>5;
    int n0 = blockIdx.x*128, m0 = blockIdx.y*128;
    int wm = (wid>>2)*64, wn = (wid&3)*32;
    float acc[4][4][4];
    #pragma unroll
    for (int a = 0; a < 4; a++)
        #pragma unroll
        for (int b = 0; b < 4; b++)
            #pragma unroll
            for (int c = 0; c < 4; c++) acc[a][b][c] = 0.f;
    int arow = lane & 15,                  akh = (lane>>4)*8;
    int brow = ((lane>>4)<<3)+(lane&7),    bkh = ((lane>>3)&1)*8;
    #pragma unroll
    for (int it = 0; it < 2; it++){
        int ch = tid + it*256;
        int row = ch>>2, kc = (ch&3)*8;
        u32 so = (u32)(row*LDS2 + kc)*2;
        *(uint4*)(sm+so)     = *(const uint4*)(g_x  + (size_t)(m0+row)*K2DIM + kc);
        *(uint4*)(sm+so+ASZ) = *(const uint4*)(g_Bh + (size_t)(n0+row)*K2DIM + kc);
    }
    __syncthreads();
    const int NSt = K2DIM/32;   // 96
    uint4 rg[4];
    for (int s = 0; s < NSt; s++){
        int cur = s & 1;
        if (s + 1 < NSt){
            int k0 = (s+1)*32;
            #pragma unroll
            for (int it = 0; it < 2; it++){
                int ch = tid + it*256;
                int row = ch>>2, kc = (ch&3)*8;
                rg[it*2+0] = *(const uint4*)(g_x  + (size_t)(m0+row)*K2DIM + k0 + kc);
                rg[it*2+1] = *(const uint4*)(g_Bh + (size_t)(n0+row)*K2DIM + k0 + kc);
            }
        }
        u32 sb = smb + (u32)cur*STG;
        #pragma unroll
        for (int kh = 0; kh < 2; kh++){
            u32 ah[4][4];
            #pragma unroll
            for (int mt = 0; mt < 4; mt++){
                u32 ad = sb + (u32)(((wm + mt*16 + arow)*LDS2) + kh*16 + akh)*2;
                LDSM4(ah[mt], ad);
            }
            u32 bh[4][2];
            #pragma unroll
            for (int g = 0; g < 2; g++){
                u32 ad = sb + ASZ + (u32)(((wn + g*16 + brow)*LDS2) + kh*16 + bkh)*2;
                u32 t[4]; LDSM4(t, ad);
                bh[2*g][0]=t[0]; bh[2*g][1]=t[1]; bh[2*g+1][0]=t[2]; bh[2*g+1][1]=t[3];
            }
            #pragma unroll
            for (int mt = 0; mt < 4; mt++)
                #pragma unroll
                for (int nt = 0; nt < 4; nt++)
                    MMAF16(acc[mt][nt], ah[mt], bh[nt][0], bh[nt][1]);
        }
        if (s + 1 < NSt){
            u32 nb = (u32)(cur^1)*STG;
            #pragma unroll
            for (int it = 0; it < 2; it++){
                int ch = tid + it*256;
                int row = ch>>2, kc = (ch&3)*8;
                u32 so = nb + (u32)(row*LDS2 + kc)*2;
                *(uint4*)(sm+so)     = rg[it*2+0];
                *(uint4*)(sm+so+ASZ) = rg[it*2+1];
            }
        }
        __syncthreads();
    }
    int rbase = m0 + wm + (lane>>2);
    int cbase = n0 + wn + (lane&3)*2;
    #pragma unroll
    for (int mt = 0; mt < 4; mt++)
        #pragma unroll
        for (int nt = 0; nt < 4; nt++){
            int c = cbase + nt*8;
            #pragma unroll
            for (int half = 0; half < 2; half++){
                int r = rbase + mt*16 + half*8;
                __half2 hp = __floats2half2_rn(acc[mt][nt][half*2], acc[mt][nt][half*2+1]);
                *reinterpret_cast<u32*>(g_Wh + (size_t)r*HID + c) = *reinterpret_cast<u32*>(&hp);
            }
        }
}

// -------- K6: max-shifted attention weights (fp16) + denominators -----------
__global__ void k_aw(){
    __shared__ float s2s[NN];
    __shared__ unsigned aws[8][64];
    int tid = threadIdx.x, wid = tid>>5, lane = tid&31;
    int row0 = blockIdx.x*8;
    int b = row0 >> 11;
    for (int i = tid; i < NN; i += 256) s2s[i] = g_s2[b*NN + i];
    for (int i = tid; i < 512; i += 256) aws[i>>6][i&63] = g_adjbits[(size_t)row0*64 + i];
    __syncthreads();
    int row = row0 + wid;
    float s1r = g_s1[row];
    __half* awp = g_aw + (size_t)row*NN;
    // pass 1: row max of leaky(s1+s2) over neighbors
    float m = -1e30f;
    for (int w = 0; w < 64; w++){
        unsigned word = aws[wid][w];
        if ((word >> lane) & 1u)
            m = fmaxf(m, leakyf(s1r + s2s[w*32 + lane]));
    }
    #pragma unroll
    for (int o = 16; o; o >>= 1) m = fmaxf(m, __shfl_xor_sync(0xffffffffu, m, o));
    // pass 2: exp(x - m), den, fp16 store
    float den = 0.f;
    for (int w = 0; w < 64; w++){
        unsigned word = aws[wid][w];
        int col = w*32 + lane;
        float wv = 0.f;
        if ((word >> lane) & 1u){
            wv = __expf(leakyf(s1r + s2s[col]) - m);
            den += wv;
        }
        awp[col] = __float2half(wv);
    }
    #pragma unroll
    for (int o = 16; o; o >>= 1) den += __shfl_xor_sync(0xffffffffu, den, o);
    if (lane == 0) g_den[row] = den;
}

// -------- K7: fp16 HMMA attention GEMM + elu + mean pool --------------------
#define ALDA 40
#define BLDB 136
#define AT_A (128*ALDA*2)
#define AT_B (32*BLDB*2)
#define AT_ST (AT_A + AT_B)
#define ATT_SMEM (2*AT_ST)

__global__ void __launch_bounds__(256,2) k_attn_mma(float* __restrict__ out){
    extern __shared__ char sm[];
    __shared__ float colsum[128];
    u32 smb = smem_u32(sm);
    int tid = threadIdx.x, lane = tid&31, wid = tid>>5;
    int it = blockIdx.x, ct = blockIdx.y, b = blockIdx.z;
    int grow0 = b*NN + it*128;
    int wm = (wid>>2)*64, wn = (wid&3)*32;
    if (tid < 128) colsum[tid] = 0.f;
    float acc[4][4][4];
    #pragma unroll
    for (int a = 0; a < 4; a++)
        #pragma unroll
        for (int b2 = 0; b2 < 4; b2++)
            #pragma unroll
            for (int c = 0; c < 4; c++) acc[a][b2][c] = 0.f;
    const __half* Abase = g_aw + (size_t)grow0*NN;
    const __half* Bbase = g_Wh + (size_t)(b*NN)*HID + ct*128;
    int arow = lane&15, akh = (lane>>4)*8;
    int bkr = lane&15, bnh = (lane>>4)*8;
    #pragma unroll
    for (int it2 = 0; it2 < 2; it2++){
        int ch = tid + it2*256;
        int row = ch>>2, kc = (ch&3)*8;
        *(uint4*)(sm + (u32)(row*ALDA + kc)*2) = *(const uint4*)(Abase + (size_t)row*NN + kc);
        int kr = ch>>4, cc = (ch&15)*8;
        *(uint4*)(sm + AT_A + (u32)(kr*BLDB + cc)*2) = *(const uint4*)(Bbase + (size_t)kr*HID + cc);
    }
    __syncthreads();
    const int NSt = NN/32;  // 64
    uint4 rg[4];
    for (int s = 0; s < NSt; s++){
        int cur = s & 1;
        if (s + 1 < NSt){
            int k0 = (s+1)*32;
            #pragma unroll
            for (int it2 = 0; it2 < 2; it2++){
                int ch = tid + it2*256;
                int row = ch>>2, kc = (ch&3)*8;
                rg[it2*2+0] = *(const uint4*)(Abase + (size_t)row*NN + k0 + kc);
                int kr = ch>>4, cc = (ch&15)*8;
                rg[it2*2+1] = *(const uint4*)(Bbase + (size_t)(k0+kr)*HID + cc);
            }
        }
        u32 sb = smb + (u32)cur*AT_ST;
        #pragma unroll
        for (int kh = 0; kh < 2; kh++){
            u32 ah[4][4];
            #pragma unroll
            for (int mt = 0; mt < 4; mt++){
                u32 ad = sb + (u32)(((wm + mt*16 + arow)*ALDA) + kh*16 + akh)*2;
                LDSM4(ah[mt], ad);
            }
            u32 bh[4][2];
            #pragma unroll
            for (int g = 0; g < 2; g++){
                u32 ad = sb + AT_A + (u32)(((kh*16 + bkr)*BLDB) + wn + g*16 + bnh)*2;
                u32 t[4];  LDSM4T(t, ad);
                bh[2*g][0]=t[0]; bh[2*g][1]=t[1]; bh[2*g+1][0]=t[2]; bh[2*g+1][1]=t[3];
            }
            #pragma unroll
            for (int mt = 0; mt < 4; mt++)
                #pragma unroll
                for (int nt = 0; nt < 4; nt++)
                    MMAF16(acc[mt][nt], ah[mt], bh[nt][0], bh[nt][1]);
        }
        if (s + 1 < NSt){
            u32 nb = (u32)(cur^1)*AT_ST;
            #pragma unroll
            for (int it2 = 0; it2 < 2; it2++){
                int ch = tid + it2*256;
                int row = ch>>2, kc = (ch&3)*8;
                *(uint4*)(sm + nb + (u32)(row*ALDA + kc)*2) = rg[it2*2+0];
                int kr = ch>>4, cc = (ch&15)*8;
                *(uint4*)(sm + nb + AT_A + (u32)(kr*BLDB + cc)*2) = rg[it2*2+1];
            }
        }
        __syncthreads();
    }
    float invd[4][2];
    #pragma unroll
    for (int mt = 0; mt < 4; mt++){
        int r = grow0 + wm + mt*16 + (lane>>2);
        float d0 = g_den[r], d1 = g_den[r+8];
        invd[mt][0] = d0 > 0.f ? 1.f/d0 : 0.f;
        invd[mt][1] = d1 > 0.f ? 1.f/d1 : 0.f;
    }
    #pragma unroll
    for (int nt = 0; nt < 4; nt++){
        float cs0 = 0.f, cs1 = 0.f;
        #pragma unroll
        for (int mt = 0; mt < 4; mt++){
            cs0 += eluf(acc[mt][nt][0]*invd[mt][0]) + eluf(acc[mt][nt][2]*invd[mt][1]);
            cs1 += eluf(acc[mt][nt][1]*invd[mt][0]) + eluf(acc[mt][nt][3]*invd[mt][1]);
        }
        int c = wn + nt*8 + (lane&3)*2;
        atomicAdd(&colsum[c], cs0);
        atomicAdd(&colsum[c+1], cs1);
    }
    __syncthreads();
    if (tid < 128)
        atomicAdd(&out[b*HID + ct*128 + tid], colsum[tid] * (1.f/(float)NN));
}

// -------- launch -------------------------------------------------------------
extern "C" void kernel_launch(void* const* d_in, const int* in_sizes, int n_in,
                              void* d_out, int out_size){
    const int*   nf     = (const int*)d_in[0];
    const int*   adj    = (const int*)d_in[1];
    const float* embed  = (const float*)d_in[2];
    const float* Wheads = (const float*)d_in[3];
    const float* aheads = (const float*)d_in[4];
    const float* Wout   = (const float*)d_in[5];
    const float* aout   = (const float*)d_in[6];
    float* out = (float*)d_out;

    cudaFuncSetAttribute(k_gemm_mma, cudaFuncAttributeMaxDynamicSharedMemorySize, GMM_SMEM);
    cudaFuncSetAttribute(k_attn_mma, cudaFuncAttributeMaxDynamicSharedMemorySize, ATT_SMEM);

    k_zero<<<64, 256>>>(out);
    k_T   <<<dim3(6, 4), 128>>>(embed, Wheads);
    k_pre2<<<1, 64>>>(aheads);
    k_adj <<<2048, 256>>>(nf, adj);
    k_prepB<<<384, 256>>>(Wout, aout);
    k_l1  <<<dim3(128, 24), 256>>>(nf);
    k_aw  <<<2048, 256>>>();
    k_gemm_mma<<<dim3(6, 128), 256, GMM_SMEM>>>();
    k_attn_mma<<<dim3(16, 6, 8), 256, ATT_SMEM>>>(out);
}